// round 15
// baseline (speedup 1.0000x reference)
#include <cuda_runtime.h>
#include <cuda_bf16.h>
#include <cuda_fp16.h>
#include <cstdint>
#include <math.h>

// ---------------- problem constants ----------------
#define BS     256
#define CE     22
#define T1     1000
#define D2     96
#define KW     12
#define T2     989
#define T2P    992
#define EP     3
#define INS    32
#define PP     8
#define OUTS   16
#define NSWEEP 6
#define NB1    500
#define NB2    1024
#define NBN2   253184.0    // BS * T2

typedef unsigned long long ull;

// ---------------- scratch ----------------
__device__ __half g_h2[(size_t)BS * D2 * T2P];
__device__ float g_S [BS * EP * INS * INS];
__device__ float g_Up[BS * EP * INS * PP];
__device__ float g_QQt[BS * EP * OUTS * OUTS];
__device__ float g_KKt[BS * EP * OUTS * OUTS];
__device__ float g_Vp [BS * OUTS * OUTS];
__device__ float g_ps1 [CE * NB1], g_ps1q[CE * NB1];
__device__ float g_ps2 [D2 * NB2], g_ps2q[D2 * NB2];
__device__ __align__(16) __half g_Aw[2 * 12 * 96 * 24];
__device__ float g_W1p[CE * CE];
__device__ float g_c1f[CE];

// ---------------- helpers ----------------
__device__ __forceinline__ ull ffma2(ull a, ull b, ull c) {
    ull d;
    asm("fma.rn.f32x2 %0, %1, %2, %3;" : "=l"(d) : "l"(a), "l"(b), "l"(c));
    return d;
}
__device__ __forceinline__ ull pack2(float x) {
    ull r;
    asm("mov.b64 %0, {%1, %1};" : "=l"(r) : "f"(x));
    return r;
}
__device__ __forceinline__ ull pack2p(float a, float b) {
    ull r;
    asm("mov.b64 %0, {%1, %2};" : "=l"(r) : "f"(a), "f"(b));
    return r;
}
__device__ __forceinline__ void unpack2(ull v, float& lo, float& hi) {
    asm("mov.b64 {%0, %1}, %2;" : "=f"(lo), "=f"(hi) : "l"(v));
}
__device__ __forceinline__ uint32_t smem_u32(const void* p) {
    uint32_t a;
    asm("{ .reg .u64 t; cvta.to.shared.u64 t, %1; cvt.u32.u64 %0, t; }" : "=r"(a) : "l"(p));
    return a;
}
__device__ __forceinline__ uint32_t pack_h2(__half a, __half b) {
    __half2 h = __halves2half2(a, b);
    return *reinterpret_cast<uint32_t*>(&h);
}

#define MMA16816(d, a0, a1, a2, a3, b0, b1) \
    asm volatile("mma.sync.aligned.m16n8k16.row.col.f32.f16.f16.f32 " \
        "{%0,%1,%2,%3}, {%4,%5,%6,%7}, {%8,%9}, {%0,%1,%2,%3};" \
        : "+f"((d)[0]), "+f"((d)[1]), "+f"((d)[2]), "+f"((d)[3]) \
        : "r"(a0), "r"(a1), "r"(a2), "r"(a3), "r"(b0), "r"(b1))
#define MMA16808(d, a0, a1, b0) \
    asm volatile("mma.sync.aligned.m16n8k8.row.col.f32.f16.f16.f32 " \
        "{%0,%1,%2,%3}, {%4,%5}, {%6}, {%0,%1,%2,%3};" \
        : "+f"((d)[0]), "+f"((d)[1]), "+f"((d)[2]), "+f"((d)[3]) \
        : "r"(a0), "r"(a1), "r"(b0))
#define LDSM_X4(r0, r1, r2, r3, addr) \
    asm volatile("ldmatrix.sync.aligned.m8n8.x4.shared.b16 {%0,%1,%2,%3}, [%4];" \
        : "=r"(r0), "=r"(r1), "=r"(r2), "=r"(r3) : "r"(addr))
#define LDSM_X2(r0, r1, addr) \
    asm volatile("ldmatrix.sync.aligned.m8n8.x2.shared.b16 {%0,%1}, [%2];" \
        : "=r"(r0), "=r"(r1) : "r"(addr))

// ================= conv1 stats only =================
__global__ void __launch_bounds__(128) k_conv1s(
        const float* __restrict__ x, const float* __restrict__ w1,
        float* __restrict__ ps, float* __restrict__ psq) {
    __shared__ float sW[CE * CE];
    __shared__ float wb[CE][4], wb2[CE][4];
    int tid = threadIdx.x, lane = tid & 31, wrp = tid >> 5;
    for (int i = tid; i < CE * CE; i += 128) sW[i] = w1[i];
    __syncthreads();
    int idx = blockIdx.x * 128 + tid;
    int b = idx / 250, t0 = (idx - b * 250) * 4;

    ull xv[CE][2];
#pragma unroll
    for (int c = 0; c < CE; c++) {
        float4 q = *(const float4*)(x + (b * CE + c) * T1 + t0);
        xv[c][0] = pack2p(q.x, q.y);
        xv[c][1] = pack2p(q.z, q.w);
    }
#pragma unroll
    for (int o = 0; o < CE; o++) {
        ull s0 = 0ull, s1 = 0ull;
#pragma unroll
        for (int c = 0; c < CE; c++) {
            ull wv = pack2(sW[o * CE + c]);
            s0 = ffma2(wv, xv[c][0], s0);
            s1 = ffma2(wv, xv[c][1], s1);
        }
        float a0, a1v, a2v, a3;
        unpack2(s0, a0, a1v); unpack2(s1, a2v, a3);
        float sm = a0 + a1v + a2v + a3;
        float sq = a0 * a0 + a1v * a1v + a2v * a2v + a3 * a3;
#pragma unroll
        for (int off = 16; off > 0; off >>= 1) {
            sm += __shfl_down_sync(0xffffffffu, sm, off);
            sq += __shfl_down_sync(0xffffffffu, sq, off);
        }
        if (lane == 0) { wb[o][wrp] = sm; wb2[o][wrp] = sq; }
    }
    __syncthreads();
    if (tid < CE) {
        float a = 0.f, bq = 0.f;
#pragma unroll
        for (int w = 0; w < 4; w++) { a += wb[tid][w]; bq += wb2[tid][w]; }
        ps [tid * NB1 + blockIdx.x] = a;
        psq[tid * NB1 + blockIdx.x] = bq;
    }
}

// ================= finalize BN1 -> folded W1'; + conv2 weight prep =================
__global__ void k_finprep(const float* __restrict__ ps, const float* __restrict__ psq,
                          const float* __restrict__ gamma, const float* __restrict__ beta,
                          const float* __restrict__ w1, const float* __restrict__ w2,
                          float* __restrict__ w1p, float* __restrict__ c1f,
                          __half* __restrict__ aw) {
    int blk = blockIdx.x, tid = threadIdx.x;
    if (blk < CE) {
        int ch = blk;
        double s = 0.0, s2 = 0.0;
        for (int i = tid; i < NB1; i += 256) {
            s  += (double)ps [ch * NB1 + i];
            s2 += (double)psq[ch * NB1 + i];
        }
        __shared__ double rs[256], rs2[256];
        __shared__ float sa1, sc1v;
        rs[tid] = s; rs2[tid] = s2;
        __syncthreads();
        for (int off = 128; off > 0; off >>= 1) {
            if (tid < off) { rs[tid] += rs[tid + off]; rs2[tid] += rs2[tid + off]; }
            __syncthreads();
        }
        if (tid == 0) {
            double n = (double)BS * (double)T1;
            double mu  = rs[0] / n;
            double var = rs2[0] / n - mu * mu;
            double av  = (double)gamma[ch] / sqrt(var + 1e-5);
            sa1 = (float)av;
            sc1v = beta[ch] - (float)(mu * av);
        }
        __syncthreads();
        if (tid < CE) w1p[ch * CE + tid] = sa1 * w1[ch * CE + tid];
        if (tid == 0) c1f[ch] = sc1v;
    } else {
        int kap = blk - CE;
        for (int i = tid; i < 96 * 24; i += 256) {
            int o = i / 24, cs = i - o * 24;
            float v = (cs < 22) ? w2[o * 264 + cs * 12 + kap] : 0.f;
            __half h = __float2half_rn(v);
            aw[kap * 2304 + i] = h;
            aw[27648 + kap * 2304 + i] = __float2half_rn(v - __half2float(h));
        }
    }
}

// ================= conv2: on-the-fly conv1+BN1+ELU, 12 shifted HMMA GEMMs =================
#define SMX_STR 40
#define SMA_STR 24
#define XROWS   272
#define OFF_XTL 21760
#define OFF_AW  43520
#define OFF_SXF 154112
#define OFF_W1  (OFF_SXF + 22 * 276 * 4)
#define OFF_C1  (OFF_W1 + 484 * 4)
#define SMEM_C2 (OFF_C1 + 128)

__global__ void __launch_bounds__(512, 1) k_conv2_hmma(
        const float* __restrict__ x, const __half* __restrict__ gaw,
        const float* __restrict__ w1p, const float* __restrict__ c1f,
        __half* __restrict__ h2, float* __restrict__ ps, float* __restrict__ psq) {
    extern __shared__ char smc[];
    __shared__ float wsum[8][96], wsq[8][96];
    uint32_t smb = smem_u32(smc);
    int tid = threadIdx.x, lane = tid & 31, w = tid >> 5;
    int mg = w & 1, ng = w >> 1;
    int b = blockIdx.x, ty = blockIdx.y;
    int t0 = ty * 256;

    __half* xth = (__half*)(smc);
    __half* xtl = (__half*)(smc + OFF_XTL);
    float*  sxf = (float*)(smc + OFF_SXF);
    float*  sw1 = (float*)(smc + OFF_W1);
    float*  sc1 = (float*)(smc + OFF_C1);

    for (int i = tid; i < CE * XROWS; i += 512) {
        int c = i / XROWS, t = i - c * XROWS;
        int gt = t0 + t;
        sxf[c * 276 + t] = (gt < T1) ? x[(b * CE + c) * T1 + gt] : 0.f;
    }
    if (tid < 484) sw1[tid] = w1p[tid];
    if (tid < CE) sc1[tid] = c1f[tid];
    for (int i = tid; i < XROWS * 2; i += 512) {
        int t = i >> 1, c = 22 + (i & 1);
        xth[t * SMX_STR + c] = __float2half_rn(0.f);
        xtl[t * SMX_STR + c] = __float2half_rn(0.f);
    }
    {
        uint4* dst = (uint4*)(smc + OFF_AW);
        const uint4* src = (const uint4*)gaw;
        for (int i = tid; i < 6912; i += 512) dst[i] = src[i];
    }
    __syncthreads();

    for (int i = tid; i < CE * (XROWS / 2); i += 512) {
        int c = i / (XROWS / 2), tp = i - c * (XROWS / 2);
        int t = 2 * tp;
        ull h = pack2(sc1[c]);
#pragma unroll
        for (int cp = 0; cp < CE; cp++) {
            ull xx = *(const ull*)(sxf + cp * 276 + t);
            h = ffma2(pack2(sw1[c * CE + cp]), xx, h);
        }
        float v0, v1;
        unpack2(h, v0, v1);
        v0 = v0 > 0.f ? v0 : expm1f(v0);
        v1 = v1 > 0.f ? v1 : expm1f(v1);
        __half h0 = __float2half_rn(v0), h1v = __float2half_rn(v1);
        xth[t * SMX_STR + c] = h0;
        xth[(t + 1) * SMX_STR + c] = h1v;
        xtl[t * SMX_STR + c] = __float2half_rn(v0 - __half2float(h0));
        xtl[(t + 1) * SMX_STR + c] = __float2half_rn(v1 - __half2float(h1v));
    }
    __syncthreads();

    float acc[3][4][4];
#pragma unroll
    for (int m = 0; m < 3; m++)
#pragma unroll
        for (int nt = 0; nt < 4; nt++)
#pragma unroll
            for (int e = 0; e < 4; e++) acc[m][nt][e] = 0.f;

    uint32_t l7 = lane & 7;
    uint32_t bgrp = lane >> 3;
    uint32_t brow4 = l7 + ((bgrp >> 1) << 3);
    uint32_t bcol4 = (bgrp & 1) << 4;
    uint32_t trow4 = (bgrp << 3) + l7;
    uint32_t arow4 = l7 + ((bgrp & 1) << 3);
    uint32_t acol4 = (bgrp >> 1) << 4;
    uint32_t row2 = l7 + ((bgrp & 1) << 3);

    uint32_t xh_b = smb, xl_b = smb + OFF_XTL;
    uint32_t ah_b = smb + OFF_AW, al_b = smb + OFF_AW + 55296;
    int mbase = mg * 48;

#pragma unroll 1
    for (int kap = 0; kap < 12; kap++) {
        int tb = ng * 32 + kap;
        uint32_t Bh[2][4], Bl[2][4], Th[4], Tl[4];
#pragma unroll
        for (int hh = 0; hh < 2; hh++) {
            uint32_t ad = xh_b + (tb + hh * 16 + brow4) * (SMX_STR * 2) + bcol4;
            LDSM_X4(Bh[hh][0], Bh[hh][1], Bh[hh][2], Bh[hh][3], ad);
            uint32_t adl = xl_b + (tb + hh * 16 + brow4) * (SMX_STR * 2) + bcol4;
            LDSM_X4(Bl[hh][0], Bl[hh][1], Bl[hh][2], Bl[hh][3], adl);
        }
        {
            uint32_t ad = xh_b + (tb + trow4) * (SMX_STR * 2) + 32;
            LDSM_X4(Th[0], Th[1], Th[2], Th[3], ad);
            uint32_t adl = xl_b + (tb + trow4) * (SMX_STR * 2) + 32;
            LDSM_X4(Tl[0], Tl[1], Tl[2], Tl[3], adl);
        }
        uint32_t akap_h = ah_b + kap * 4608;
        uint32_t akap_l = al_b + kap * 4608;
#pragma unroll
        for (int mt = 0; mt < 3; mt++) {
            int ro = mbase + mt * 16;
            uint32_t ah0, ah1, ah2, ah3, al0, al1, al2, al3;
            uint32_t ath0, ath1, atl0, atl1;
            uint32_t ad = akap_h + (ro + arow4) * (SMA_STR * 2) + acol4;
            LDSM_X4(ah0, ah1, ah2, ah3, ad);
            uint32_t adl = akap_l + (ro + arow4) * (SMA_STR * 2) + acol4;
            LDSM_X4(al0, al1, al2, al3, adl);
            uint32_t adt = akap_h + (ro + row2) * (SMA_STR * 2) + 32;
            LDSM_X2(ath0, ath1, adt);
            uint32_t adtl = akap_l + (ro + row2) * (SMA_STR * 2) + 32;
            LDSM_X2(atl0, atl1, adtl);
#pragma unroll
            for (int nt = 0; nt < 4; nt++) {
                uint32_t b0 = Bh[nt >> 1][2 * (nt & 1)];
                uint32_t b1 = Bh[nt >> 1][2 * (nt & 1) + 1];
                uint32_t c0 = Bl[nt >> 1][2 * (nt & 1)];
                uint32_t c1v = Bl[nt >> 1][2 * (nt & 1) + 1];
                MMA16816(acc[mt][nt], ah0, ah1, ah2, ah3, b0, b1);
                MMA16816(acc[mt][nt], al0, al1, al2, al3, b0, b1);
                MMA16816(acc[mt][nt], ah0, ah1, ah2, ah3, c0, c1v);
                MMA16808(acc[mt][nt], ath0, ath1, Th[nt]);
                MMA16808(acc[mt][nt], atl0, atl1, Th[nt]);
                MMA16808(acc[mt][nt], ath0, ath1, Tl[nt]);
            }
        }
    }

#pragma unroll
    for (int mt = 0; mt < 3; mt++) {
        int r0 = mbase + mt * 16 + (lane >> 2), r1 = r0 + 8;
        float s0 = 0.f, q0 = 0.f, s1 = 0.f, q1 = 0.f;
#pragma unroll
        for (int nt = 0; nt < 4; nt++) {
            int tg = t0 + ng * 32 + nt * 8 + 2 * (lane & 3);
            float d0 = acc[mt][nt][0], d1 = acc[mt][nt][1];
            float d2 = acc[mt][nt][2], d3 = acc[mt][nt][3];
            __half* p0 = h2 + ((size_t)b * D2 + r0) * T2P + tg;
            __half* p1 = h2 + ((size_t)b * D2 + r1) * T2P + tg;
            if (tg + 1 < T2) {
                *(__half2*)p0 = __floats2half2_rn(d0, d1);
                *(__half2*)p1 = __floats2half2_rn(d2, d3);
                s0 += d0 + d1; q0 += d0 * d0 + d1 * d1;
                s1 += d2 + d3; q1 += d2 * d2 + d3 * d3;
            } else if (tg < T2) {
                p0[0] = __float2half_rn(d0); p1[0] = __float2half_rn(d2);
                s0 += d0; q0 += d0 * d0;
                s1 += d2; q1 += d2 * d2;
            }
        }
#pragma unroll
        for (int off = 1; off <= 2; off <<= 1) {
            s0 += __shfl_xor_sync(0xffffffffu, s0, off);
            q0 += __shfl_xor_sync(0xffffffffu, q0, off);
            s1 += __shfl_xor_sync(0xffffffffu, s1, off);
            q1 += __shfl_xor_sync(0xffffffffu, q1, off);
        }
        if ((lane & 3) == 0) {
            wsum[ng][r0] = s0; wsq[ng][r0] = q0;
            wsum[ng][r1] = s1; wsq[ng][r1] = q1;
        }
    }
    __syncthreads();
    if (tid < 96) {
        float s = 0.f, q = 0.f;
#pragma unroll
        for (int k = 0; k < 8; k++) { s += wsum[k][tid]; q += wsq[k][tid]; }
        int blk = b * 4 + ty;
        ps [(size_t)tid * NB2 + blk] = s;
        psq[(size_t)tid * NB2 + blk] = q;
    }
}

// ================= k_cov: BN2 finalize + fused BN/ELU staging + chunked HMMA Gram =================
#define CVS 520    // smem row stride in halves (1040 B)
#define SMEM_CV (32 * CVS * 2)   // 33280 B
__global__ void __launch_bounds__(256) k_cov(
        const __half* __restrict__ h2, const float* __restrict__ ps2,
        const float* __restrict__ psq2, const float* __restrict__ bn2g,
        const float* __restrict__ bn2b, float* __restrict__ S) {
    extern __shared__ __align__(16) char dsm[];
    __half* sX = (__half*)dsm;              // 32 x 520 halves
    float* red = (float*)dsm;               // overlay after MMA: 8 x 1024 floats
    __shared__ double sred[32][8][2];
    __shared__ float sa[32], sc[32];
    int bm = blockIdx.x;
    int b = bm / EP, m = bm - b * EP;
    int tid = threadIdx.x, lane = tid & 31, w = tid >> 5;

    // ---- BN2 finalize (32 channels; ps2 is L2-resident) ----
    {
        int r = tid >> 3, part = tid & 7;
        const float* pp = ps2 + (size_t)(m * 32 + r) * NB2 + part * 128;
        const float* pq = psq2 + (size_t)(m * 32 + r) * NB2 + part * 128;
        float s = 0.f, s2 = 0.f;
        for (int k = 0; k < 128; k++) { s += pp[k]; s2 += pq[k]; }
        sred[r][part][0] = (double)s;
        sred[r][part][1] = (double)s2;
    }
    __syncthreads();
    if (tid < 32) {
        double s = 0.0, s2 = 0.0;
        for (int k = 0; k < 8; k++) { s += sred[tid][k][0]; s2 += sred[tid][k][1]; }
        double mu  = s / NBN2;
        double var = s2 / NBN2 - mu * mu;
        double av  = (double)bn2g[m * 32 + tid] / sqrt(var + 1e-5);
        sa[tid] = (float)av;
        sc[tid] = bn2b[m * 32 + tid] - (float)(mu * av);
    }
    __syncthreads();

    float acc[2][4][4];
#pragma unroll
    for (int mt = 0; mt < 2; mt++)
#pragma unroll
        for (int nt = 0; nt < 4; nt++)
#pragma unroll
            for (int e = 0; e < 4; e++) acc[mt][nt][e] = 0.f;

    uint32_t base = smem_u32(sX);
    uint32_t l7 = lane & 7, bgrp = lane >> 3;
    uint32_t arow = l7 + ((bgrp & 1) << 3);
    uint32_t acol = (bgrp >> 1) << 4;
    uint32_t bcol = (bgrp & 1) << 4;

#pragma unroll 1
    for (int chk = 0; chk < 2; chk++) {
        __syncthreads();    // WAR vs previous chunk's MMA
        for (int idx = tid; idx < 32 * 62; idx += 256) {
            int r = idx / 62, cj = idx - r * 62;
            uint4 v = *((const uint4*)(h2 + ((size_t)b * D2 + m * 32 + r) * T2P)
                        + chk * 62 + cj);
            __half* hv = (__half*)&v;
            float a = sa[r], c = sc[r];
            int tb = chk * 496 + cj * 8;
#pragma unroll
            for (int e = 0; e < 8; e++) {
                float f = __half2float(hv[e]);
                f = fmaf(f, a, c);
                f = f > 0.f ? f : (__expf(f) - 1.f);
                if (tb + e >= T2) f = 0.f;
                hv[e] = __float2half_rn(f);
            }
            *((uint4*)(sX + r * CVS) + cj) = v;
        }
        __syncthreads();
        for (int k = w; k < 31; k += 8) {
            uint32_t kb = base + (uint32_t)k * 32;
            uint32_t af[2][4];
#pragma unroll
            for (int mt = 0; mt < 2; mt++)
                LDSM_X4(af[mt][0], af[mt][1], af[mt][2], af[mt][3],
                        kb + (mt * 16 + arow) * (CVS * 2) + acol);
            uint32_t bf[4][2];
#pragma unroll
            for (int nt = 0; nt < 4; nt++)
                LDSM_X2(bf[nt][0], bf[nt][1],
                        kb + (nt * 8 + l7) * (CVS * 2) + bcol);
#pragma unroll
            for (int mt = 0; mt < 2; mt++)
#pragma unroll
                for (int nt = 0; nt < 4; nt++)
                    MMA16816(acc[mt][nt], af[mt][0], af[mt][1], af[mt][2], af[mt][3],
                             bf[nt][0], bf[nt][1]);
        }
    }
    __syncthreads();   // sX dead -> reuse as reduction buffer

    {
        int rb = lane >> 2, cb = 2 * (lane & 3);
        float* rw = red + w * 1024;
#pragma unroll
        for (int mt = 0; mt < 2; mt++)
#pragma unroll
            for (int nt = 0; nt < 4; nt++) {
                int row = mt * 16 + rb, col = nt * 8 + cb;
                rw[row * 32 + col]           = acc[mt][nt][0];
                rw[row * 32 + col + 1]       = acc[mt][nt][1];
                rw[(row + 8) * 32 + col]     = acc[mt][nt][2];
                rw[(row + 8) * 32 + col + 1] = acc[mt][nt][3];
            }
    }
    __syncthreads();
    float* Sp = S + (size_t)bm * 1024;
    for (int o = tid; o < 1024; o += 256) {
        float s = 0.f;
#pragma unroll
        for (int k2 = 0; k2 < 8; k2++) s += red[k2 * 1024 + o];
        Sp[o] = s;
    }
}

// ================= Jacobi (smem, threshold-skip, 2 barriers/round) =================
__global__ void __launch_bounds__(256) k_jacobi(
        const float* __restrict__ S, float* __restrict__ Up) {
    __shared__ float A[32][33], V[32][33];
    __shared__ int sidx[8];
    int bm = blockIdx.x, tid = threadIdx.x;

    for (int i = tid; i < 1024; i += 256) {
        int r = i >> 5, cc = i & 31;
        A[r][cc] = S[(size_t)bm * 1024 + i];
        V[r][cc] = (r == cc) ? 1.f : 0.f;
    }
    __syncthreads();

    int g = tid >> 4, l = tid & 15;
    for (int sw = 0; sw < NSWEEP; sw++) {
        for (int r = 0; r < 31; r++) {
            int p = (g == 0) ? 0 : ((g - 1 + r) % 31) + 1;
            int q = ((30 - g + r) % 31) + 1;
            if (p > q) { int tmp = p; p = q; q = tmp; }
            float app = A[p][p], aqq = A[q][q], apq = A[p][q];
            bool skip = (apq * apq <= 1e-14f * fabsf(app * aqq) + 1e-38f);
            float cv = 1.f, sv = 0.f;
            if (!skip) {
                float tau = (aqq - app) / (2.f * apq);
                float tt = (tau >= 0.f ? 1.f : -1.f) / (fabsf(tau) + sqrtf(1.f + tau * tau));
                cv = rsqrtf(1.f + tt * tt);
                sv = tt * cv;
            }
            if (!skip) {
                float ap = A[p][l], aq = A[q][l];
                A[p][l] = cv * ap - sv * aq;
                A[q][l] = sv * ap + cv * aq;
                int j1 = l + 16;
                ap = A[p][j1]; aq = A[q][j1];
                A[p][j1] = cv * ap - sv * aq;
                A[q][j1] = sv * ap + cv * aq;
            }
            __syncthreads();
            if (!skip) {
#pragma unroll
                for (int s2 = 0; s2 < 2; s2++) {
                    int ii = l + 16 * s2;
                    float ap = A[ii][p], aq = A[ii][q];
                    A[ii][p] = cv * ap - sv * aq;
                    A[ii][q] = sv * ap + cv * aq;
                    float vp = V[ii][p], vq = V[ii][q];
                    V[ii][p] = cv * vp - sv * vq;
                    V[ii][q] = sv * vp + cv * vq;
                }
            }
            __syncthreads();
        }
    }

    if (tid == 0) {
        float vals[32];
        for (int i = 0; i < 32; i++) vals[i] = A[i][i];
        for (int j = 0; j < 8; j++) {
            int am = 0; float mv = vals[0];
            for (int i = 1; i < 32; i++) if (vals[i] > mv) { mv = vals[i]; am = i; }
            sidx[j] = am; vals[am] = -3.4e38f;
        }
    }
    __syncthreads();
    {
        int cc = tid >> 3, j = tid & 7;
        Up[bm * (INS * PP) + tid] = V[cc][sidx[j]];
    }
}

// ================= projectors via Cholesky =================
__global__ void k_proj(const float* __restrict__ Up, const float* __restrict__ wq,
                       const float* __restrict__ wk, const float* __restrict__ wv,
                       float* __restrict__ QQt, float* __restrict__ KKt,
                       float* __restrict__ Vp) {
    __shared__ float sUp[32][8], sM[16][8], sG[8][8], sY[16][8];
    int bm = blockIdx.x, tid = threadIdx.x;
    int b = bm / EP, m = bm - b * EP;
    for (int i = tid; i < 256; i += 128) sUp[i >> 3][i & 7] = Up[bm * 256 + i];

    int nmat = (m == 2) ? 3 : 2;
    for (int mat = 0; mat < nmat; mat++) {
        const float* W = (mat == 0) ? wq : (mat == 1) ? wk : wv;
        __syncthreads();
        {
            int r = tid >> 3, p = tid & 7;
            float s = 0.f;
            for (int cc = 0; cc < 32; cc++) s = fmaf(W[r * 32 + cc], sUp[cc][p], s);
            sM[r][p] = s;
        }
        __syncthreads();
        if (tid < 64) {
            int i = tid >> 3, j = tid & 7;
            float s = 0.f;
            for (int rr = 0; rr < 16; rr++) s = fmaf(sM[rr][i], sM[rr][j], s);
            sG[i][j] = s;
        }
        __syncthreads();
        if (tid == 0) {
            for (int k = 0; k < 8; k++) {
                float lkk = sqrtf(sG[k][k]);
                sG[k][k] = lkk;
                float inv = 1.f / lkk;
                for (int i = k + 1; i < 8; i++) sG[i][k] *= inv;
                for (int j = k + 1; j < 8; j++)
                    for (int i = j; i < 8; i++) sG[i][j] -= sG[i][k] * sG[j][k];
            }
        }
        __syncthreads();
        if (tid < 16) {
            int r = tid;
            for (int i = 0; i < 8; i++) {
                float v = sM[r][i];
                for (int j = 0; j < i; j++) v -= sG[i][j] * sY[r][j];
                sY[r][i] = v / sG[i][i];
            }
        }
        __syncthreads();
        float* outp = (mat == 0) ? (QQt + bm * 256)
                    : (mat == 1) ? (KKt + bm * 256)
                                 : (Vp + b * 256);
        for (int e = tid; e < 256; e += 128) {
            int u = e >> 4, v = e & 15;
            float s = 0.f;
#pragma unroll
            for (int i = 0; i < 8; i++) s = fmaf(sY[u][i], sY[v][i], s);
            outp[e] = s;
        }
    }
}

// ================= E, softmax, final linear =================
__global__ void k_final(const float* __restrict__ QQt, const float* __restrict__ KKt,
                        const float* __restrict__ Vp, const float* __restrict__ lw,
                        const float* __restrict__ lb, float* __restrict__ out) {
    int b = blockIdx.x, tid = threadIdx.x;
    __shared__ float sQ[3 * 256], sK[3 * 256], sV[256];
    __shared__ float sE[9], swv[3];
    __shared__ float red[8];
    __shared__ float red12[12][8];
    for (int i = tid; i < 768; i += 256) {
        sQ[i] = QQt[b * 768 + i];
        sK[i] = KKt[b * 768 + i];
    }
    sV[tid] = Vp[b * 256 + tid];
    __syncthreads();

    int u = tid >> 4, v = tid & 15;
    for (int ij = 0; ij < 9; ij++) {
        int i = ij / 3, j = ij - 3 * i;
        const float* Qj = sQ + j * 256;
        const float* Ki = sK + i * 256;
        float dd = 0.f;
#pragma unroll
        for (int w = 0; w < 16; w++) {
            float du = Qj[u * 16 + w] - Ki[u * 16 + w];
            float dv = Qj[v * 16 + w] - Ki[v * 16 + w];
            dd = fmaf(du, dv, dd);
        }
        float val = dd * dd;
        for (int off = 16; off > 0; off >>= 1) val += __shfl_down_sync(0xffffffffu, val, off);
        if ((tid & 31) == 0) red[tid >> 5] = val;
        __syncthreads();
        if (tid == 0) {
            float s = 0.f;
            for (int w = 0; w < 8; w++) s += red[w];
            sE[ij] = sqrtf(s);
        }
        __syncthreads();
    }
    if (tid == 0) {
        for (int j = 0; j < 3; j++) {
            float s0 = 1.f / (1.f + log1pf(sE[0 * 3 + j]));
            float s1 = 1.f / (1.f + log1pf(sE[1 * 3 + j]));
            float s2 = 1.f / (1.f + log1pf(sE[2 * 3 + j]));
            float mx = fmaxf(s0, fmaxf(s1, s2));
            float e0 = expf(s0 - mx), e1 = expf(s1 - mx), e2 = expf(s2 - mx);
            swv[j] = e2 / (e0 + e1 + e2);
        }
    }
    __syncthreads();

    float vv = sV[tid];
    float part[12];
#pragma unroll
    for (int r = 0; r < 4; r++)
#pragma unroll
        for (int j = 0; j < 3; j++)
            part[r * 3 + j] = lw[r * 768 + j * 256 + tid] * vv;
#pragma unroll
    for (int kk = 0; kk < 12; kk++) {
        float val = part[kk];
        for (int off = 16; off > 0; off >>= 1) val += __shfl_down_sync(0xffffffffu, val, off);
        if ((tid & 31) == 0) red12[kk][tid >> 5] = val;
    }
    __syncthreads();
    if (tid < 4) {
        float o = lb[tid];
        for (int j = 0; j < 3; j++) {
            float ds = 0.f;
            for (int w = 0; w < 8; w++) ds += red12[tid * 3 + j][w];
            o = fmaf(swv[j], ds, o);
        }
        out[b * 4 + tid] = o;
    }
}

// ================= launch =================
extern "C" void kernel_launch(void* const* d_in, const int* in_sizes, int n_in,
                              void* d_out, int out_size) {
    const float* x      = (const float*)d_in[0];
    const float* conv1w = (const float*)d_in[1];
    const float* bn1g   = (const float*)d_in[3];
    const float* bn1b   = (const float*)d_in[4];
    const float* conv2w = (const float*)d_in[5];
    const float* bn2g   = (const float*)d_in[7];
    const float* bn2b   = (const float*)d_in[8];
    const float* wq     = (const float*)d_in[9];
    const float* wk     = (const float*)d_in[10];
    const float* wv     = (const float*)d_in[11];
    const float* linw   = (const float*)d_in[12];
    const float* linb   = (const float*)d_in[13];
    float* out = (float*)d_out;

    float *S, *Up, *QQt, *KKt, *Vp, *ps1, *ps1q, *ps2, *ps2q, *w1p, *c1f;
    __half *aw, *h2;
    cudaGetSymbolAddress((void**)&h2,  g_h2);
    cudaGetSymbolAddress((void**)&S,   g_S);
    cudaGetSymbolAddress((void**)&Up,  g_Up);
    cudaGetSymbolAddress((void**)&QQt, g_QQt);
    cudaGetSymbolAddress((void**)&KKt, g_KKt);
    cudaGetSymbolAddress((void**)&Vp,  g_Vp);
    cudaGetSymbolAddress((void**)&ps1, g_ps1);
    cudaGetSymbolAddress((void**)&ps1q,g_ps1q);
    cudaGetSymbolAddress((void**)&ps2, g_ps2);
    cudaGetSymbolAddress((void**)&ps2q,g_ps2q);
    cudaGetSymbolAddress((void**)&aw,  g_Aw);
    cudaGetSymbolAddress((void**)&w1p, g_W1p);
    cudaGetSymbolAddress((void**)&c1f, g_c1f);

    cudaFuncSetAttribute(k_conv2_hmma, cudaFuncAttributeMaxDynamicSharedMemorySize, SMEM_C2);
    cudaFuncSetAttribute(k_cov, cudaFuncAttributeMaxDynamicSharedMemorySize, SMEM_CV);

    k_conv1s    <<<NB1, 128>>>(x, conv1w, ps1, ps1q);
    k_finprep   <<<34, 256>>>(ps1, ps1q, bn1g, bn1b, conv1w, conv2w, w1p, c1f, aw);
    k_conv2_hmma<<<dim3(BS, 4), 512, SMEM_C2>>>(x, aw, w1p, c1f, h2, ps2, ps2q);
    k_cov       <<<BS * EP, 256, SMEM_CV>>>(h2, ps2, ps2q, bn2g, bn2b, S);
    k_jacobi    <<<BS * EP, 256>>>(S, Up);
    k_proj      <<<BS * EP, 128>>>(Up, wq, wk, wv, QQt, KKt, Vp);
    k_final     <<<BS, 256>>>(QQt, KKt, Vp, linw, linb, out);
}

// round 16
// speedup vs baseline: 1.3196x; 1.3196x over previous
#include <cuda_runtime.h>
#include <cuda_bf16.h>
#include <cuda_fp16.h>
#include <cstdint>
#include <math.h>

// ---------------- problem constants ----------------
#define BS     256
#define CE     22
#define T1     1000
#define D2     96
#define KW     12
#define T2     989
#define T2P    992
#define EP     3
#define INS    32
#define PP     8
#define OUTS   16
#define NSWEEP 6
#define NB1    500
#define NB2    1024
#define NBN2   253184.0    // BS * T2

typedef unsigned long long ull;

// ---------------- scratch ----------------
__device__ __half g_h2[(size_t)BS * D2 * T2P];
__device__ float g_QQt[BS * EP * OUTS * OUTS];
__device__ float g_KKt[BS * EP * OUTS * OUTS];
__device__ float g_Vp [BS * OUTS * OUTS];
__device__ float g_ps1 [CE * NB1], g_ps1q[CE * NB1];
__device__ float g_ps2 [D2 * NB2], g_ps2q[D2 * NB2];
__device__ __align__(16) __half g_Aw[2 * 12 * 96 * 24];
__device__ float g_W1p[CE * CE];
__device__ float g_c1f[CE];

// ---------------- helpers ----------------
__device__ __forceinline__ ull ffma2(ull a, ull b, ull c) {
    ull d;
    asm("fma.rn.f32x2 %0, %1, %2, %3;" : "=l"(d) : "l"(a), "l"(b), "l"(c));
    return d;
}
__device__ __forceinline__ ull pack2(float x) {
    ull r;
    asm("mov.b64 %0, {%1, %1};" : "=l"(r) : "f"(x));
    return r;
}
__device__ __forceinline__ ull pack2p(float a, float b) {
    ull r;
    asm("mov.b64 %0, {%1, %2};" : "=l"(r) : "f"(a), "f"(b));
    return r;
}
__device__ __forceinline__ void unpack2(ull v, float& lo, float& hi) {
    asm("mov.b64 {%0, %1}, %2;" : "=f"(lo), "=f"(hi) : "l"(v));
}
__device__ __forceinline__ uint32_t smem_u32(const void* p) {
    uint32_t a;
    asm("{ .reg .u64 t; cvta.to.shared.u64 t, %1; cvt.u32.u64 %0, t; }" : "=r"(a) : "l"(p));
    return a;
}
__device__ __forceinline__ uint32_t pack_h2(__half a, __half b) {
    __half2 h = __halves2half2(a, b);
    return *reinterpret_cast<uint32_t*>(&h);
}

#define MMA16816(d, a0, a1, a2, a3, b0, b1) \
    asm volatile("mma.sync.aligned.m16n8k16.row.col.f32.f16.f16.f32 " \
        "{%0,%1,%2,%3}, {%4,%5,%6,%7}, {%8,%9}, {%0,%1,%2,%3};" \
        : "+f"((d)[0]), "+f"((d)[1]), "+f"((d)[2]), "+f"((d)[3]) \
        : "r"(a0), "r"(a1), "r"(a2), "r"(a3), "r"(b0), "r"(b1))
#define MMA16808(d, a0, a1, b0) \
    asm volatile("mma.sync.aligned.m16n8k8.row.col.f32.f16.f16.f32 " \
        "{%0,%1,%2,%3}, {%4,%5}, {%6}, {%0,%1,%2,%3};" \
        : "+f"((d)[0]), "+f"((d)[1]), "+f"((d)[2]), "+f"((d)[3]) \
        : "r"(a0), "r"(a1), "r"(b0))
#define LDSM_X4(r0, r1, r2, r3, addr) \
    asm volatile("ldmatrix.sync.aligned.m8n8.x4.shared.b16 {%0,%1,%2,%3}, [%4];" \
        : "=r"(r0), "=r"(r1), "=r"(r2), "=r"(r3) : "r"(addr))
#define LDSM_X2(r0, r1, addr) \
    asm volatile("ldmatrix.sync.aligned.m8n8.x2.shared.b16 {%0,%1}, [%2];" \
        : "=r"(r0), "=r"(r1) : "r"(addr))

// ================= conv1 stats only =================
__global__ void __launch_bounds__(128) k_conv1s(
        const float* __restrict__ x, const float* __restrict__ w1,
        float* __restrict__ ps, float* __restrict__ psq) {
    __shared__ float sW[CE * CE];
    __shared__ float wb[CE][4], wb2[CE][4];
    int tid = threadIdx.x, lane = tid & 31, wrp = tid >> 5;
    for (int i = tid; i < CE * CE; i += 128) sW[i] = w1[i];
    __syncthreads();
    int idx = blockIdx.x * 128 + tid;
    int b = idx / 250, t0 = (idx - b * 250) * 4;

    ull xv[CE][2];
#pragma unroll
    for (int c = 0; c < CE; c++) {
        float4 q = *(const float4*)(x + (b * CE + c) * T1 + t0);
        xv[c][0] = pack2p(q.x, q.y);
        xv[c][1] = pack2p(q.z, q.w);
    }
#pragma unroll
    for (int o = 0; o < CE; o++) {
        ull s0 = 0ull, s1 = 0ull;
#pragma unroll
        for (int c = 0; c < CE; c++) {
            ull wv = pack2(sW[o * CE + c]);
            s0 = ffma2(wv, xv[c][0], s0);
            s1 = ffma2(wv, xv[c][1], s1);
        }
        float a0, a1v, a2v, a3;
        unpack2(s0, a0, a1v); unpack2(s1, a2v, a3);
        float sm = a0 + a1v + a2v + a3;
        float sq = a0 * a0 + a1v * a1v + a2v * a2v + a3 * a3;
#pragma unroll
        for (int off = 16; off > 0; off >>= 1) {
            sm += __shfl_down_sync(0xffffffffu, sm, off);
            sq += __shfl_down_sync(0xffffffffu, sq, off);
        }
        if (lane == 0) { wb[o][wrp] = sm; wb2[o][wrp] = sq; }
    }
    __syncthreads();
    if (tid < CE) {
        float a = 0.f, bq = 0.f;
#pragma unroll
        for (int w = 0; w < 4; w++) { a += wb[tid][w]; bq += wb2[tid][w]; }
        ps [tid * NB1 + blockIdx.x] = a;
        psq[tid * NB1 + blockIdx.x] = bq;
    }
}

// ================= finalize BN1 -> folded W1'; + conv2 weight prep =================
__global__ void k_finprep(const float* __restrict__ ps, const float* __restrict__ psq,
                          const float* __restrict__ gamma, const float* __restrict__ beta,
                          const float* __restrict__ w1, const float* __restrict__ w2,
                          float* __restrict__ w1p, float* __restrict__ c1f,
                          __half* __restrict__ aw) {
    int blk = blockIdx.x, tid = threadIdx.x;
    if (blk < CE) {
        int ch = blk;
        double s = 0.0, s2 = 0.0;
        for (int i = tid; i < NB1; i += 256) {
            s  += (double)ps [ch * NB1 + i];
            s2 += (double)psq[ch * NB1 + i];
        }
        __shared__ double rs[256], rs2[256];
        __shared__ float sa1, sc1v;
        rs[tid] = s; rs2[tid] = s2;
        __syncthreads();
        for (int off = 128; off > 0; off >>= 1) {
            if (tid < off) { rs[tid] += rs[tid + off]; rs2[tid] += rs2[tid + off]; }
            __syncthreads();
        }
        if (tid == 0) {
            double n = (double)BS * (double)T1;
            double mu  = rs[0] / n;
            double var = rs2[0] / n - mu * mu;
            double av  = (double)gamma[ch] / sqrt(var + 1e-5);
            sa1 = (float)av;
            sc1v = beta[ch] - (float)(mu * av);
        }
        __syncthreads();
        if (tid < CE) w1p[ch * CE + tid] = sa1 * w1[ch * CE + tid];
        if (tid == 0) c1f[ch] = sc1v;
    } else {
        int kap = blk - CE;
        for (int i = tid; i < 96 * 24; i += 256) {
            int o = i / 24, cs = i - o * 24;
            float v = (cs < 22) ? w2[o * 264 + cs * 12 + kap] : 0.f;
            __half h = __float2half_rn(v);
            aw[kap * 2304 + i] = h;
            aw[27648 + kap * 2304 + i] = __float2half_rn(v - __half2float(h));
        }
    }
}

// ================= conv2: on-the-fly conv1+BN1+ELU, 12 shifted HMMA GEMMs =================
#define SMX_STR 40
#define SMA_STR 24
#define XROWS   272
#define OFF_XTL 21760
#define OFF_AW  43520
#define OFF_SXF 154112
#define OFF_W1  (OFF_SXF + 22 * 276 * 4)
#define OFF_C1  (OFF_W1 + 484 * 4)
#define SMEM_C2 (OFF_C1 + 128)

__global__ void __launch_bounds__(512, 1) k_conv2_hmma(
        const float* __restrict__ x, const __half* __restrict__ gaw,
        const float* __restrict__ w1p, const float* __restrict__ c1f,
        __half* __restrict__ h2, float* __restrict__ ps, float* __restrict__ psq) {
    extern __shared__ char smc[];
    __shared__ float wsum[8][96], wsq[8][96];
    uint32_t smb = smem_u32(smc);
    int tid = threadIdx.x, lane = tid & 31, w = tid >> 5;
    int mg = w & 1, ng = w >> 1;
    int b = blockIdx.x, ty = blockIdx.y;
    int t0 = ty * 256;

    __half* xth = (__half*)(smc);
    __half* xtl = (__half*)(smc + OFF_XTL);
    float*  sxf = (float*)(smc + OFF_SXF);
    float*  sw1 = (float*)(smc + OFF_W1);
    float*  sc1 = (float*)(smc + OFF_C1);

    for (int i = tid; i < CE * XROWS; i += 512) {
        int c = i / XROWS, t = i - c * XROWS;
        int gt = t0 + t;
        sxf[c * 276 + t] = (gt < T1) ? x[(b * CE + c) * T1 + gt] : 0.f;
    }
    if (tid < 484) sw1[tid] = w1p[tid];
    if (tid < CE) sc1[tid] = c1f[tid];
    for (int i = tid; i < XROWS * 2; i += 512) {
        int t = i >> 1, c = 22 + (i & 1);
        xth[t * SMX_STR + c] = __float2half_rn(0.f);
        xtl[t * SMX_STR + c] = __float2half_rn(0.f);
    }
    {
        uint4* dst = (uint4*)(smc + OFF_AW);
        const uint4* src = (const uint4*)gaw;
        for (int i = tid; i < 6912; i += 512) dst[i] = src[i];
    }
    __syncthreads();

    for (int i = tid; i < CE * (XROWS / 2); i += 512) {
        int c = i / (XROWS / 2), tp = i - c * (XROWS / 2);
        int t = 2 * tp;
        ull h = pack2(sc1[c]);
#pragma unroll
        for (int cp = 0; cp < CE; cp++) {
            ull xx = *(const ull*)(sxf + cp * 276 + t);
            h = ffma2(pack2(sw1[c * CE + cp]), xx, h);
        }
        float v0, v1;
        unpack2(h, v0, v1);
        v0 = v0 > 0.f ? v0 : expm1f(v0);
        v1 = v1 > 0.f ? v1 : expm1f(v1);
        __half h0 = __float2half_rn(v0), h1v = __float2half_rn(v1);
        xth[t * SMX_STR + c] = h0;
        xth[(t + 1) * SMX_STR + c] = h1v;
        xtl[t * SMX_STR + c] = __float2half_rn(v0 - __half2float(h0));
        xtl[(t + 1) * SMX_STR + c] = __float2half_rn(v1 - __half2float(h1v));
    }
    __syncthreads();

    float acc[3][4][4];
#pragma unroll
    for (int m = 0; m < 3; m++)
#pragma unroll
        for (int nt = 0; nt < 4; nt++)
#pragma unroll
            for (int e = 0; e < 4; e++) acc[m][nt][e] = 0.f;

    uint32_t l7 = lane & 7;
    uint32_t bgrp = lane >> 3;
    uint32_t brow4 = l7 + ((bgrp >> 1) << 3);
    uint32_t bcol4 = (bgrp & 1) << 4;
    uint32_t trow4 = (bgrp << 3) + l7;
    uint32_t arow4 = l7 + ((bgrp & 1) << 3);
    uint32_t acol4 = (bgrp >> 1) << 4;
    uint32_t row2 = l7 + ((bgrp & 1) << 3);

    uint32_t xh_b = smb, xl_b = smb + OFF_XTL;
    uint32_t ah_b = smb + OFF_AW, al_b = smb + OFF_AW + 55296;
    int mbase = mg * 48;

#pragma unroll 1
    for (int kap = 0; kap < 12; kap++) {
        int tb = ng * 32 + kap;
        uint32_t Bh[2][4], Bl[2][4], Th[4], Tl[4];
#pragma unroll
        for (int hh = 0; hh < 2; hh++) {
            uint32_t ad = xh_b + (tb + hh * 16 + brow4) * (SMX_STR * 2) + bcol4;
            LDSM_X4(Bh[hh][0], Bh[hh][1], Bh[hh][2], Bh[hh][3], ad);
            uint32_t adl = xl_b + (tb + hh * 16 + brow4) * (SMX_STR * 2) + bcol4;
            LDSM_X4(Bl[hh][0], Bl[hh][1], Bl[hh][2], Bl[hh][3], adl);
        }
        {
            uint32_t ad = xh_b + (tb + trow4) * (SMX_STR * 2) + 32;
            LDSM_X4(Th[0], Th[1], Th[2], Th[3], ad);
            uint32_t adl = xl_b + (tb + trow4) * (SMX_STR * 2) + 32;
            LDSM_X4(Tl[0], Tl[1], Tl[2], Tl[3], adl);
        }
        uint32_t akap_h = ah_b + kap * 4608;
        uint32_t akap_l = al_b + kap * 4608;
#pragma unroll
        for (int mt = 0; mt < 3; mt++) {
            int ro = mbase + mt * 16;
            uint32_t ah0, ah1, ah2, ah3, al0, al1, al2, al3;
            uint32_t ath0, ath1, atl0, atl1;
            uint32_t ad = akap_h + (ro + arow4) * (SMA_STR * 2) + acol4;
            LDSM_X4(ah0, ah1, ah2, ah3, ad);
            uint32_t adl = akap_l + (ro + arow4) * (SMA_STR * 2) + acol4;
            LDSM_X4(al0, al1, al2, al3, adl);
            uint32_t adt = akap_h + (ro + row2) * (SMA_STR * 2) + 32;
            LDSM_X2(ath0, ath1, adt);
            uint32_t adtl = akap_l + (ro + row2) * (SMA_STR * 2) + 32;
            LDSM_X2(atl0, atl1, adtl);
#pragma unroll
            for (int nt = 0; nt < 4; nt++) {
                uint32_t b0 = Bh[nt >> 1][2 * (nt & 1)];
                uint32_t b1 = Bh[nt >> 1][2 * (nt & 1) + 1];
                uint32_t c0 = Bl[nt >> 1][2 * (nt & 1)];
                uint32_t c1v = Bl[nt >> 1][2 * (nt & 1) + 1];
                MMA16816(acc[mt][nt], ah0, ah1, ah2, ah3, b0, b1);
                MMA16816(acc[mt][nt], al0, al1, al2, al3, b0, b1);
                MMA16816(acc[mt][nt], ah0, ah1, ah2, ah3, c0, c1v);
                MMA16808(acc[mt][nt], ath0, ath1, Th[nt]);
                MMA16808(acc[mt][nt], atl0, atl1, Th[nt]);
                MMA16808(acc[mt][nt], ath0, ath1, Tl[nt]);
            }
        }
    }

#pragma unroll
    for (int mt = 0; mt < 3; mt++) {
        int r0 = mbase + mt * 16 + (lane >> 2), r1 = r0 + 8;
        float s0 = 0.f, q0 = 0.f, s1 = 0.f, q1 = 0.f;
#pragma unroll
        for (int nt = 0; nt < 4; nt++) {
            int tg = t0 + ng * 32 + nt * 8 + 2 * (lane & 3);
            float d0 = acc[mt][nt][0], d1 = acc[mt][nt][1];
            float d2 = acc[mt][nt][2], d3 = acc[mt][nt][3];
            __half* p0 = h2 + ((size_t)b * D2 + r0) * T2P + tg;
            __half* p1 = h2 + ((size_t)b * D2 + r1) * T2P + tg;
            if (tg + 1 < T2) {
                *(__half2*)p0 = __floats2half2_rn(d0, d1);
                *(__half2*)p1 = __floats2half2_rn(d2, d3);
                s0 += d0 + d1; q0 += d0 * d0 + d1 * d1;
                s1 += d2 + d3; q1 += d2 * d2 + d3 * d3;
            } else if (tg < T2) {
                p0[0] = __float2half_rn(d0); p1[0] = __float2half_rn(d2);
                s0 += d0; q0 += d0 * d0;
                s1 += d2; q1 += d2 * d2;
            }
        }
#pragma unroll
        for (int off = 1; off <= 2; off <<= 1) {
            s0 += __shfl_xor_sync(0xffffffffu, s0, off);
            q0 += __shfl_xor_sync(0xffffffffu, q0, off);
            s1 += __shfl_xor_sync(0xffffffffu, s1, off);
            q1 += __shfl_xor_sync(0xffffffffu, q1, off);
        }
        if ((lane & 3) == 0) {
            wsum[ng][r0] = s0; wsq[ng][r0] = q0;
            wsum[ng][r1] = s1; wsq[ng][r1] = q1;
        }
    }
    __syncthreads();
    if (tid < 96) {
        float s = 0.f, q = 0.f;
#pragma unroll
        for (int k = 0; k < 8; k++) { s += wsum[k][tid]; q += wsq[k][tid]; }
        int blk = b * 4 + ty;
        ps [(size_t)tid * NB2 + blk] = s;
        psq[(size_t)tid * NB2 + blk] = q;
    }
}

// ================= k_elu: BN2 finalize + in-place BN+ELU on h2 (fast exp) =================
__global__ void __launch_bounds__(256) k_elu(
        __half* __restrict__ h2, const float* __restrict__ ps2,
        const float* __restrict__ psq2, const float* __restrict__ bn2g,
        const float* __restrict__ bn2b) {
    int ch = blockIdx.x, qt = blockIdx.y;
    int tid = threadIdx.x;
    __shared__ double rs[256], rs2[256];
    __shared__ float saf, scf;
    double s = 0.0, s2 = 0.0;
    for (int i = tid; i < NB2; i += 256) {
        s  += (double)ps2 [(size_t)ch * NB2 + i];
        s2 += (double)psq2[(size_t)ch * NB2 + i];
    }
    rs[tid] = s; rs2[tid] = s2;
    __syncthreads();
    for (int off = 128; off > 0; off >>= 1) {
        if (tid < off) { rs[tid] += rs[tid + off]; rs2[tid] += rs2[tid + off]; }
        __syncthreads();
    }
    if (tid == 0) {
        double mu  = rs[0] / NBN2;
        double var = rs2[0] / NBN2 - mu * mu;
        double av  = (double)bn2g[ch] / sqrt(var + 1e-5);
        saf = (float)av;
        scf = bn2b[ch] - (float)(mu * av);
    }
    __syncthreads();
    float a = saf, c = scf;

    for (int idx = tid; idx < 64 * 124; idx += 256) {
        int r = idx / 124, cj = idx - r * 124;
        int b = qt * 64 + r;
        uint4* p = (uint4*)(h2 + ((size_t)b * D2 + ch) * T2P) + cj;
        uint4 v = *p;
        __half* hv = (__half*)&v;
        int tb = cj * 8;
#pragma unroll
        for (int e = 0; e < 8; e++) {
            float f = __half2float(hv[e]);
            f = fmaf(f, a, c);
            f = f > 0.f ? f : (__expf(f) - 1.f);
            if (tb + e >= T2) f = 0.f;
            hv[e] = __float2half_rn(f);
        }
        *p = v;
    }
}

// ================= fused cov (chunked HMMA) + Jacobi + projectors =================
#define CVS 520
#define SMEM_CV (32 * CVS * 2)   // 33280 B dynamic
__global__ void __launch_bounds__(256) k_coveig(
        const __half* __restrict__ h2e,
        const float* __restrict__ wq, const float* __restrict__ wk,
        const float* __restrict__ wv,
        float* __restrict__ QQt, float* __restrict__ KKt,
        float* __restrict__ Vp) {
    extern __shared__ __align__(16) char dsm[];
    __half* sX = (__half*)dsm;
    float* red = (float*)dsm;
    __shared__ float A[32][33], V[32][33];
    __shared__ int sidx[8];
    __shared__ float sUp[32][8], sM[16][8], sG[8][8], sY[16][8];
    int bm = blockIdx.x;
    int b = bm / EP, m = bm - b * EP;
    int tid = threadIdx.x, lane = tid & 31, w = tid >> 5;

    for (int i = tid; i < 1024; i += 256) {
        int r = i >> 5, cc = i & 31;
        V[r][cc] = (r == cc) ? 1.f : 0.f;
    }

    // ---- chunked HMMA Gram ----
    float acc[2][4][4];
#pragma unroll
    for (int mt = 0; mt < 2; mt++)
#pragma unroll
        for (int nt = 0; nt < 4; nt++)
#pragma unroll
            for (int e = 0; e < 4; e++) acc[mt][nt][e] = 0.f;

    uint32_t base = smem_u32(sX);
    uint32_t l7 = lane & 7, bgrp = lane >> 3;
    uint32_t arow = l7 + ((bgrp & 1) << 3);
    uint32_t acol = (bgrp >> 1) << 4;
    uint32_t bcol = (bgrp & 1) << 4;

#pragma unroll 1
    for (int chk = 0; chk < 2; chk++) {
        __syncthreads();
        for (int idx = tid; idx < 32 * 62; idx += 256) {
            int r = idx / 62, cj = idx - r * 62;
            *((uint4*)(sX + r * CVS) + cj) =
                *((const uint4*)(h2e + ((size_t)b * D2 + m * 32 + r) * T2P)
                  + chk * 62 + cj);
        }
        __syncthreads();
        for (int k = w; k < 31; k += 8) {
            uint32_t kb = base + (uint32_t)k * 32;
            uint32_t af[2][4];
#pragma unroll
            for (int mt = 0; mt < 2; mt++)
                LDSM_X4(af[mt][0], af[mt][1], af[mt][2], af[mt][3],
                        kb + (mt * 16 + arow) * (CVS * 2) + acol);
            uint32_t bf[4][2];
#pragma unroll
            for (int nt = 0; nt < 4; nt++)
                LDSM_X2(bf[nt][0], bf[nt][1],
                        kb + (nt * 8 + l7) * (CVS * 2) + bcol);
#pragma unroll
            for (int mt = 0; mt < 2; mt++)
#pragma unroll
                for (int nt = 0; nt < 4; nt++)
                    MMA16816(acc[mt][nt], af[mt][0], af[mt][1], af[mt][2], af[mt][3],
                             bf[nt][0], bf[nt][1]);
        }
    }
    __syncthreads();   // sX dead -> reuse as reduction buffer

    {
        int rb = lane >> 2, cb = 2 * (lane & 3);
        float* rw = red + w * 1024;
#pragma unroll
        for (int mt = 0; mt < 2; mt++)
#pragma unroll
            for (int nt = 0; nt < 4; nt++) {
                int row = mt * 16 + rb, col = nt * 8 + cb;
                rw[row * 32 + col]           = acc[mt][nt][0];
                rw[row * 32 + col + 1]       = acc[mt][nt][1];
                rw[(row + 8) * 32 + col]     = acc[mt][nt][2];
                rw[(row + 8) * 32 + col + 1] = acc[mt][nt][3];
            }
    }
    __syncthreads();
    for (int o = tid; o < 1024; o += 256) {
        float s = 0.f;
#pragma unroll
        for (int k2 = 0; k2 < 8; k2++) s += red[k2 * 1024 + o];
        A[o >> 5][o & 31] = s;
    }
    __syncthreads();

    // ---- Jacobi (threshold-skip, 2 barriers/round) ----
    {
        int g = tid >> 4, l = tid & 15;
        for (int sw = 0; sw < NSWEEP; sw++) {
            for (int r = 0; r < 31; r++) {
                int p = (g == 0) ? 0 : ((g - 1 + r) % 31) + 1;
                int q = ((30 - g + r) % 31) + 1;
                if (p > q) { int tmp = p; p = q; q = tmp; }
                float app = A[p][p], aqq = A[q][q], apq = A[p][q];
                bool skip = (apq * apq <= 1e-14f * fabsf(app * aqq) + 1e-38f);
                float cv = 1.f, sv = 0.f;
                if (!skip) {
                    float tau = (aqq - app) / (2.f * apq);
                    float tt = (tau >= 0.f ? 1.f : -1.f) / (fabsf(tau) + sqrtf(1.f + tau * tau));
                    cv = rsqrtf(1.f + tt * tt);
                    sv = tt * cv;
                }
                if (!skip) {
                    float ap = A[p][l], aq = A[q][l];
                    A[p][l] = cv * ap - sv * aq;
                    A[q][l] = sv * ap + cv * aq;
                    int j1 = l + 16;
                    ap = A[p][j1]; aq = A[q][j1];
                    A[p][j1] = cv * ap - sv * aq;
                    A[q][j1] = sv * ap + cv * aq;
                }
                __syncthreads();
                if (!skip) {
#pragma unroll
                    for (int s2 = 0; s2 < 2; s2++) {
                        int ii = l + 16 * s2;
                        float ap = A[ii][p], aq = A[ii][q];
                        A[ii][p] = cv * ap - sv * aq;
                        A[ii][q] = sv * ap + cv * aq;
                        float vp = V[ii][p], vq = V[ii][q];
                        V[ii][p] = cv * vp - sv * vq;
                        V[ii][q] = sv * vp + cv * vq;
                    }
                }
                __syncthreads();
            }
        }
    }

    if (tid == 0) {
        float vals[32];
        for (int i = 0; i < 32; i++) vals[i] = A[i][i];
        for (int j = 0; j < 8; j++) {
            int am = 0; float mv = vals[0];
            for (int i = 1; i < 32; i++) if (vals[i] > mv) { mv = vals[i]; am = i; }
            sidx[j] = am; vals[am] = -3.4e38f;
        }
    }
    __syncthreads();
    sUp[tid >> 3][tid & 7] = V[tid >> 3][sidx[tid & 7]];
    __syncthreads();

    // ---- projectors: P = M (M^T M)^{-1} M^T via Cholesky ----
    int nmat = (m == 2) ? 3 : 2;
    for (int mat = 0; mat < nmat; mat++) {
        const float* W = (mat == 0) ? wq : (mat == 1) ? wk : wv;
        if (tid < 128) {
            int r = tid >> 3, p = tid & 7;
            float s = 0.f;
            for (int cc = 0; cc < 32; cc++) s = fmaf(W[r * 32 + cc], sUp[cc][p], s);
            sM[r][p] = s;
        }
        __syncthreads();
        if (tid < 64) {
            int i = tid >> 3, j = tid & 7;
            float s = 0.f;
            for (int rr = 0; rr < 16; rr++) s = fmaf(sM[rr][i], sM[rr][j], s);
            sG[i][j] = s;
        }
        __syncthreads();
        if (tid == 0) {
            for (int k = 0; k < 8; k++) {
                float lkk = sqrtf(sG[k][k]);
                sG[k][k] = lkk;
                float inv = 1.f / lkk;
                for (int i = k + 1; i < 8; i++) sG[i][k] *= inv;
                for (int j = k + 1; j < 8; j++)
                    for (int i = j; i < 8; i++) sG[i][j] -= sG[i][k] * sG[j][k];
            }
        }
        __syncthreads();
        if (tid < 16) {
            int r = tid;
            for (int i = 0; i < 8; i++) {
                float v = sM[r][i];
                for (int j = 0; j < i; j++) v -= sG[i][j] * sY[r][j];
                sY[r][i] = v / sG[i][i];
            }
        }
        __syncthreads();
        float* outp = (mat == 0) ? (QQt + bm * 256)
                    : (mat == 1) ? (KKt + bm * 256)
                                 : (Vp + b * 256);
        {
            int u = tid >> 4, v = tid & 15;
            float s = 0.f;
#pragma unroll
            for (int i = 0; i < 8; i++) s = fmaf(sY[u][i], sY[v][i], s);
            outp[tid] = s;
        }
        __syncthreads();
    }
}

// ================= E, softmax, final linear =================
__global__ void k_final(const float* __restrict__ QQt, const float* __restrict__ KKt,
                        const float* __restrict__ Vp, const float* __restrict__ lw,
                        const float* __restrict__ lb, float* __restrict__ out) {
    int b = blockIdx.x, tid = threadIdx.x;
    __shared__ float sQ[3 * 256], sK[3 * 256], sV[256];
    __shared__ float sE[9], swv[3];
    __shared__ float red[8];
    __shared__ float red12[12][8];
    for (int i = tid; i < 768; i += 256) {
        sQ[i] = QQt[b * 768 + i];
        sK[i] = KKt[b * 768 + i];
    }
    sV[tid] = Vp[b * 256 + tid];
    __syncthreads();

    int u = tid >> 4, v = tid & 15;
    for (int ij = 0; ij < 9; ij++) {
        int i = ij / 3, j = ij - 3 * i;
        const float* Qj = sQ + j * 256;
        const float* Ki = sK + i * 256;
        float dd = 0.f;
#pragma unroll
        for (int w = 0; w < 16; w++) {
            float du = Qj[u * 16 + w] - Ki[u * 16 + w];
            float dv = Qj[v * 16 + w] - Ki[v * 16 + w];
            dd = fmaf(du, dv, dd);
        }
        float val = dd * dd;
        for (int off = 16; off > 0; off >>= 1) val += __shfl_down_sync(0xffffffffu, val, off);
        if ((tid & 31) == 0) red[tid >> 5] = val;
        __syncthreads();
        if (tid == 0) {
            float s = 0.f;
            for (int w = 0; w < 8; w++) s += red[w];
            sE[ij] = sqrtf(s);
        }
        __syncthreads();
    }
    if (tid == 0) {
        for (int j = 0; j < 3; j++) {
            float s0 = 1.f / (1.f + log1pf(sE[0 * 3 + j]));
            float s1 = 1.f / (1.f + log1pf(sE[1 * 3 + j]));
            float s2 = 1.f / (1.f + log1pf(sE[2 * 3 + j]));
            float mx = fmaxf(s0, fmaxf(s1, s2));
            float e0 = expf(s0 - mx), e1 = expf(s1 - mx), e2 = expf(s2 - mx);
            swv[j] = e2 / (e0 + e1 + e2);
        }
    }
    __syncthreads();

    float vv = sV[tid];
    float part[12];
#pragma unroll
    for (int r = 0; r < 4; r++)
#pragma unroll
        for (int j = 0; j < 3; j++)
            part[r * 3 + j] = lw[r * 768 + j * 256 + tid] * vv;
#pragma unroll
    for (int kk = 0; kk < 12; kk++) {
        float val = part[kk];
        for (int off = 16; off > 0; off >>= 1) val += __shfl_down_sync(0xffffffffu, val, off);
        if ((tid & 31) == 0) red12[kk][tid >> 5] = val;
    }
    __syncthreads();
    if (tid < 4) {
        float o = lb[tid];
        for (int j = 0; j < 3; j++) {
            float ds = 0.f;
            for (int w = 0; w < 8; w++) ds += red12[tid * 3 + j][w];
            o = fmaf(swv[j], ds, o);
        }
        out[b * 4 + tid] = o;
    }
}

// ================= launch =================
extern "C" void kernel_launch(void* const* d_in, const int* in_sizes, int n_in,
                              void* d_out, int out_size) {
    const float* x      = (const float*)d_in[0];
    const float* conv1w = (const float*)d_in[1];
    const float* bn1g   = (const float*)d_in[3];
    const float* bn1b   = (const float*)d_in[4];
    const float* conv2w = (const float*)d_in[5];
    const float* bn2g   = (const float*)d_in[7];
    const float* bn2b   = (const float*)d_in[8];
    const float* wq     = (const float*)d_in[9];
    const float* wk     = (const float*)d_in[10];
    const float* wv     = (const float*)d_in[11];
    const float* linw   = (const float*)d_in[12];
    const float* linb   = (const float*)d_in[13];
    float* out = (float*)d_out;

    float *QQt, *KKt, *Vp, *ps1, *ps1q, *ps2, *ps2q, *w1p, *c1f;
    __half *aw, *h2;
    cudaGetSymbolAddress((void**)&h2,  g_h2);
    cudaGetSymbolAddress((void**)&QQt, g_QQt);
    cudaGetSymbolAddress((void**)&KKt, g_KKt);
    cudaGetSymbolAddress((void**)&Vp,  g_Vp);
    cudaGetSymbolAddress((void**)&ps1, g_ps1);
    cudaGetSymbolAddress((void**)&ps1q,g_ps1q);
    cudaGetSymbolAddress((void**)&ps2, g_ps2);
    cudaGetSymbolAddress((void**)&ps2q,g_ps2q);
    cudaGetSymbolAddress((void**)&aw,  g_Aw);
    cudaGetSymbolAddress((void**)&w1p, g_W1p);
    cudaGetSymbolAddress((void**)&c1f, g_c1f);

    cudaFuncSetAttribute(k_conv2_hmma, cudaFuncAttributeMaxDynamicSharedMemorySize, SMEM_C2);
    cudaFuncSetAttribute(k_coveig, cudaFuncAttributeMaxDynamicSharedMemorySize, SMEM_CV);

    k_conv1s    <<<NB1, 128>>>(x, conv1w, ps1, ps1q);
    k_finprep   <<<34, 256>>>(ps1, ps1q, bn1g, bn1b, conv1w, conv2w, w1p, c1f, aw);
    k_conv2_hmma<<<dim3(BS, 4), 512, SMEM_C2>>>(x, aw, w1p, c1f, h2, ps2, ps2q);
    k_elu       <<<dim3(D2, 4), 256>>>(h2, ps2, ps2q, bn2g, bn2b);
    k_coveig    <<<BS * EP, 256, SMEM_CV>>>(h2, wq, wk, wv, QQt, KKt, Vp);
    k_final     <<<BS, 256>>>(QQt, KKt, Vp, linw, linb, out);
}

// round 17
// speedup vs baseline: 1.5451x; 1.1709x over previous
#include <cuda_runtime.h>
#include <cuda_bf16.h>
#include <cuda_fp16.h>
#include <cstdint>
#include <math.h>

// ---------------- problem constants ----------------
#define BS     256
#define CE     22
#define T1     1000
#define D2     96
#define KW     12
#define T2     989
#define T2P    992
#define EP     3
#define INS    32
#define PP     8
#define OUTS   16
#define NSWEEP 5
#define NB1    500
#define NB2    1024
#define NBN2   253184.0    // BS * T2

typedef unsigned long long ull;

// ---------------- scratch ----------------
__device__ __half g_h2[(size_t)BS * D2 * T2P];
__device__ float g_QQt[BS * EP * OUTS * OUTS];
__device__ float g_KKt[BS * EP * OUTS * OUTS];
__device__ float g_Vp [BS * OUTS * OUTS];
__device__ float g_ps1 [CE * NB1], g_ps1q[CE * NB1];
__device__ float g_ps2 [D2 * NB2], g_ps2q[D2 * NB2];
__device__ __align__(16) __half g_Aw[12 * 96 * 24];   // hi-only weights
__device__ float g_W1p[CE * CE];
__device__ float g_c1f[CE];

// ---------------- helpers ----------------
__device__ __forceinline__ ull ffma2(ull a, ull b, ull c) {
    ull d;
    asm("fma.rn.f32x2 %0, %1, %2, %3;" : "=l"(d) : "l"(a), "l"(b), "l"(c));
    return d;
}
__device__ __forceinline__ ull pack2(float x) {
    ull r;
    asm("mov.b64 %0, {%1, %1};" : "=l"(r) : "f"(x));
    return r;
}
__device__ __forceinline__ ull pack2p(float a, float b) {
    ull r;
    asm("mov.b64 %0, {%1, %2};" : "=l"(r) : "f"(a), "f"(b));
    return r;
}
__device__ __forceinline__ void unpack2(ull v, float& lo, float& hi) {
    asm("mov.b64 {%0, %1}, %2;" : "=f"(lo), "=f"(hi) : "l"(v));
}
__device__ __forceinline__ uint32_t smem_u32(const void* p) {
    uint32_t a;
    asm("{ .reg .u64 t; cvta.to.shared.u64 t, %1; cvt.u32.u64 %0, t; }" : "=r"(a) : "l"(p));
    return a;
}
__device__ __forceinline__ uint32_t pack_h2(__half a, __half b) {
    __half2 h = __halves2half2(a, b);
    return *reinterpret_cast<uint32_t*>(&h);
}

#define MMA16816(d, a0, a1, a2, a3, b0, b1) \
    asm volatile("mma.sync.aligned.m16n8k16.row.col.f32.f16.f16.f32 " \
        "{%0,%1,%2,%3}, {%4,%5,%6,%7}, {%8,%9}, {%0,%1,%2,%3};" \
        : "+f"((d)[0]), "+f"((d)[1]), "+f"((d)[2]), "+f"((d)[3]) \
        : "r"(a0), "r"(a1), "r"(a2), "r"(a3), "r"(b0), "r"(b1))
#define MMA16808(d, a0, a1, b0) \
    asm volatile("mma.sync.aligned.m16n8k8.row.col.f32.f16.f16.f32 " \
        "{%0,%1,%2,%3}, {%4,%5}, {%6}, {%0,%1,%2,%3};" \
        : "+f"((d)[0]), "+f"((d)[1]), "+f"((d)[2]), "+f"((d)[3]) \
        : "r"(a0), "r"(a1), "r"(b0))
#define LDSM_X4(r0, r1, r2, r3, addr) \
    asm volatile("ldmatrix.sync.aligned.m8n8.x4.shared.b16 {%0,%1,%2,%3}, [%4];" \
        : "=r"(r0), "=r"(r1), "=r"(r2), "=r"(r3) : "r"(addr))
#define LDSM_X2(r0, r1, addr) \
    asm volatile("ldmatrix.sync.aligned.m8n8.x2.shared.b16 {%0,%1}, [%2];" \
        : "=r"(r0), "=r"(r1) : "r"(addr))

// ================= conv1 stats only =================
__global__ void __launch_bounds__(128) k_conv1s(
        const float* __restrict__ x, const float* __restrict__ w1,
        float* __restrict__ ps, float* __restrict__ psq) {
    __shared__ float sW[CE * CE];
    __shared__ float wb[CE][4], wb2[CE][4];
    int tid = threadIdx.x, lane = tid & 31, wrp = tid >> 5;
    for (int i = tid; i < CE * CE; i += 128) sW[i] = w1[i];
    __syncthreads();
    int idx = blockIdx.x * 128 + tid;
    int b = idx / 250, t0 = (idx - b * 250) * 4;

    ull xv[CE][2];
#pragma unroll
    for (int c = 0; c < CE; c++) {
        float4 q = *(const float4*)(x + (b * CE + c) * T1 + t0);
        xv[c][0] = pack2p(q.x, q.y);
        xv[c][1] = pack2p(q.z, q.w);
    }
#pragma unroll
    for (int o = 0; o < CE; o++) {
        ull s0 = 0ull, s1 = 0ull;
#pragma unroll
        for (int c = 0; c < CE; c++) {
            ull wv = pack2(sW[o * CE + c]);
            s0 = ffma2(wv, xv[c][0], s0);
            s1 = ffma2(wv, xv[c][1], s1);
        }
        float a0, a1v, a2v, a3;
        unpack2(s0, a0, a1v); unpack2(s1, a2v, a3);
        float sm = a0 + a1v + a2v + a3;
        float sq = a0 * a0 + a1v * a1v + a2v * a2v + a3 * a3;
#pragma unroll
        for (int off = 16; off > 0; off >>= 1) {
            sm += __shfl_down_sync(0xffffffffu, sm, off);
            sq += __shfl_down_sync(0xffffffffu, sq, off);
        }
        if (lane == 0) { wb[o][wrp] = sm; wb2[o][wrp] = sq; }
    }
    __syncthreads();
    if (tid < CE) {
        float a = 0.f, bq = 0.f;
#pragma unroll
        for (int w = 0; w < 4; w++) { a += wb[tid][w]; bq += wb2[tid][w]; }
        ps [tid * NB1 + blockIdx.x] = a;
        psq[tid * NB1 + blockIdx.x] = bq;
    }
}

// ================= finalize BN1 -> folded W1'; + conv2 weight prep (hi only) =================
__global__ void k_finprep(const float* __restrict__ ps, const float* __restrict__ psq,
                          const float* __restrict__ gamma, const float* __restrict__ beta,
                          const float* __restrict__ w1, const float* __restrict__ w2,
                          float* __restrict__ w1p, float* __restrict__ c1f,
                          __half* __restrict__ aw) {
    int blk = blockIdx.x, tid = threadIdx.x;
    if (blk < CE) {
        int ch = blk;
        double s = 0.0, s2 = 0.0;
        for (int i = tid; i < NB1; i += 256) {
            s  += (double)ps [ch * NB1 + i];
            s2 += (double)psq[ch * NB1 + i];
        }
        __shared__ double rs[256], rs2[256];
        __shared__ float sa1, sc1v;
        rs[tid] = s; rs2[tid] = s2;
        __syncthreads();
        for (int off = 128; off > 0; off >>= 1) {
            if (tid < off) { rs[tid] += rs[tid + off]; rs2[tid] += rs2[tid + off]; }
            __syncthreads();
        }
        if (tid == 0) {
            double n = (double)BS * (double)T1;
            double mu  = rs[0] / n;
            double var = rs2[0] / n - mu * mu;
            double av  = (double)gamma[ch] / sqrt(var + 1e-5);
            sa1 = (float)av;
            sc1v = beta[ch] - (float)(mu * av);
        }
        __syncthreads();
        if (tid < CE) w1p[ch * CE + tid] = sa1 * w1[ch * CE + tid];
        if (tid == 0) c1f[ch] = sc1v;
    } else {
        int kap = blk - CE;
        for (int i = tid; i < 96 * 24; i += 256) {
            int o = i / 24, cs = i - o * 24;
            float v = (cs < 22) ? w2[o * 264 + cs * 12 + kap] : 0.f;
            aw[kap * 2304 + i] = __float2half_rn(v);
        }
    }
}

// ================= conv2: conv1+BN1+ELU on the fly, 12 shifted HMMA GEMMs =================
// terms kept: Wh*Xh + Wh*Xl (weights fp16-rounded; dot-product rel err ~2^-12)
#define SMX_STR 40
#define SMA_STR 24
#define XROWS   272
#define OFF_XTL 21760
#define OFF_AW  43520
#define OFF_SXF (OFF_AW + 55296)          // 98816
#define OFF_W1  (OFF_SXF + 22 * 276 * 4)  // 123104
#define OFF_C1  (OFF_W1 + 484 * 4)        // 125040
#define SMEM_C2 (OFF_C1 + 128)            // 125168

__global__ void __launch_bounds__(512, 1) k_conv2_hmma(
        const float* __restrict__ x, const __half* __restrict__ gaw,
        const float* __restrict__ w1p, const float* __restrict__ c1f,
        __half* __restrict__ h2, float* __restrict__ ps, float* __restrict__ psq) {
    extern __shared__ char smc[];
    __shared__ float wsum[8][96], wsq[8][96];
    uint32_t smb = smem_u32(smc);
    int tid = threadIdx.x, lane = tid & 31, w = tid >> 5;
    int mg = w & 1, ng = w >> 1;
    int b = blockIdx.x, ty = blockIdx.y;
    int t0 = ty * 256;

    __half* xth = (__half*)(smc);
    __half* xtl = (__half*)(smc + OFF_XTL);
    float*  sxf = (float*)(smc + OFF_SXF);
    float*  sw1 = (float*)(smc + OFF_W1);
    float*  sc1 = (float*)(smc + OFF_C1);

    for (int i = tid; i < CE * XROWS; i += 512) {
        int c = i / XROWS, t = i - c * XROWS;
        int gt = t0 + t;
        sxf[c * 276 + t] = (gt < T1) ? x[(b * CE + c) * T1 + gt] : 0.f;
    }
    if (tid < 484) sw1[tid] = w1p[tid];
    if (tid < CE) sc1[tid] = c1f[tid];
    for (int i = tid; i < XROWS * 2; i += 512) {
        int t = i >> 1, c = 22 + (i & 1);
        xth[t * SMX_STR + c] = __float2half_rn(0.f);
        xtl[t * SMX_STR + c] = __float2half_rn(0.f);
    }
    {
        uint4* dst = (uint4*)(smc + OFF_AW);
        const uint4* src = (const uint4*)gaw;
        for (int i = tid; i < 3456; i += 512) dst[i] = src[i];
    }
    __syncthreads();

    for (int i = tid; i < CE * (XROWS / 2); i += 512) {
        int c = i / (XROWS / 2), tp = i - c * (XROWS / 2);
        int t = 2 * tp;
        ull h = pack2(sc1[c]);
#pragma unroll
        for (int cp = 0; cp < CE; cp++) {
            ull xx = *(const ull*)(sxf + cp * 276 + t);
            h = ffma2(pack2(sw1[c * CE + cp]), xx, h);
        }
        float v0, v1;
        unpack2(h, v0, v1);
        v0 = v0 > 0.f ? v0 : expm1f(v0);
        v1 = v1 > 0.f ? v1 : expm1f(v1);
        __half h0 = __float2half_rn(v0), h1v = __float2half_rn(v1);
        xth[t * SMX_STR + c] = h0;
        xth[(t + 1) * SMX_STR + c] = h1v;
        xtl[t * SMX_STR + c] = __float2half_rn(v0 - __half2float(h0));
        xtl[(t + 1) * SMX_STR + c] = __float2half_rn(v1 - __half2float(h1v));
    }
    __syncthreads();

    float acc[3][4][4];
#pragma unroll
    for (int m = 0; m < 3; m++)
#pragma unroll
        for (int nt = 0; nt < 4; nt++)
#pragma unroll
            for (int e = 0; e < 4; e++) acc[m][nt][e] = 0.f;

    uint32_t l7 = lane & 7;
    uint32_t bgrp = lane >> 3;
    uint32_t brow4 = l7 + ((bgrp >> 1) << 3);
    uint32_t bcol4 = (bgrp & 1) << 4;
    uint32_t trow4 = (bgrp << 3) + l7;
    uint32_t arow4 = l7 + ((bgrp & 1) << 3);
    uint32_t acol4 = (bgrp >> 1) << 4;
    uint32_t row2 = l7 + ((bgrp & 1) << 3);

    uint32_t xh_b = smb, xl_b = smb + OFF_XTL;
    uint32_t ah_b = smb + OFF_AW;
    int mbase = mg * 48;

#pragma unroll 1
    for (int kap = 0; kap < 12; kap++) {
        int tb = ng * 32 + kap;
        uint32_t Bh[2][4], Bl[2][4], Th[4], Tl[4];
#pragma unroll
        for (int hh = 0; hh < 2; hh++) {
            uint32_t ad = xh_b + (tb + hh * 16 + brow4) * (SMX_STR * 2) + bcol4;
            LDSM_X4(Bh[hh][0], Bh[hh][1], Bh[hh][2], Bh[hh][3], ad);
            uint32_t adl = xl_b + (tb + hh * 16 + brow4) * (SMX_STR * 2) + bcol4;
            LDSM_X4(Bl[hh][0], Bl[hh][1], Bl[hh][2], Bl[hh][3], adl);
        }
        {
            uint32_t ad = xh_b + (tb + trow4) * (SMX_STR * 2) + 32;
            LDSM_X4(Th[0], Th[1], Th[2], Th[3], ad);
            uint32_t adl = xl_b + (tb + trow4) * (SMX_STR * 2) + 32;
            LDSM_X4(Tl[0], Tl[1], Tl[2], Tl[3], adl);
        }
        uint32_t akap_h = ah_b + kap * 4608;
#pragma unroll
        for (int mt = 0; mt < 3; mt++) {
            int ro = mbase + mt * 16;
            uint32_t ah0, ah1, ah2, ah3, ath0, ath1;
            uint32_t ad = akap_h + (ro + arow4) * (SMA_STR * 2) + acol4;
            LDSM_X4(ah0, ah1, ah2, ah3, ad);
            uint32_t adt = akap_h + (ro + row2) * (SMA_STR * 2) + 32;
            LDSM_X2(ath0, ath1, adt);
#pragma unroll
            for (int nt = 0; nt < 4; nt++) {
                uint32_t b0 = Bh[nt >> 1][2 * (nt & 1)];
                uint32_t b1 = Bh[nt >> 1][2 * (nt & 1) + 1];
                uint32_t c0 = Bl[nt >> 1][2 * (nt & 1)];
                uint32_t c1v = Bl[nt >> 1][2 * (nt & 1) + 1];
                MMA16816(acc[mt][nt], ah0, ah1, ah2, ah3, b0, b1);
                MMA16816(acc[mt][nt], ah0, ah1, ah2, ah3, c0, c1v);
                MMA16808(acc[mt][nt], ath0, ath1, Th[nt]);
                MMA16808(acc[mt][nt], ath0, ath1, Tl[nt]);
            }
        }
    }

#pragma unroll
    for (int mt = 0; mt < 3; mt++) {
        int r0 = mbase + mt * 16 + (lane >> 2), r1 = r0 + 8;
        float s0 = 0.f, q0 = 0.f, s1 = 0.f, q1 = 0.f;
#pragma unroll
        for (int nt = 0; nt < 4; nt++) {
            int tg = t0 + ng * 32 + nt * 8 + 2 * (lane & 3);
            float d0 = acc[mt][nt][0], d1 = acc[mt][nt][1];
            float d2 = acc[mt][nt][2], d3 = acc[mt][nt][3];
            __half* p0 = h2 + ((size_t)b * D2 + r0) * T2P + tg;
            __half* p1 = h2 + ((size_t)b * D2 + r1) * T2P + tg;
            if (tg + 1 < T2) {
                *(__half2*)p0 = __floats2half2_rn(d0, d1);
                *(__half2*)p1 = __floats2half2_rn(d2, d3);
                s0 += d0 + d1; q0 += d0 * d0 + d1 * d1;
                s1 += d2 + d3; q1 += d2 * d2 + d3 * d3;
            } else if (tg < T2) {
                p0[0] = __float2half_rn(d0); p1[0] = __float2half_rn(d2);
                s0 += d0; q0 += d0 * d0;
                s1 += d2; q1 += d2 * d2;
            }
        }
#pragma unroll
        for (int off = 1; off <= 2; off <<= 1) {
            s0 += __shfl_xor_sync(0xffffffffu, s0, off);
            q0 += __shfl_xor_sync(0xffffffffu, q0, off);
            s1 += __shfl_xor_sync(0xffffffffu, s1, off);
            q1 += __shfl_xor_sync(0xffffffffu, q1, off);
        }
        if ((lane & 3) == 0) {
            wsum[ng][r0] = s0; wsq[ng][r0] = q0;
            wsum[ng][r1] = s1; wsq[ng][r1] = q1;
        }
    }
    __syncthreads();
    if (tid < 96) {
        float s = 0.f, q = 0.f;
#pragma unroll
        for (int k = 0; k < 8; k++) { s += wsum[k][tid]; q += wsq[k][tid]; }
        int blk = b * 4 + ty;
        ps [(size_t)tid * NB2 + blk] = s;
        psq[(size_t)tid * NB2 + blk] = q;
    }
}

// ================= k_elu: BN2 finalize + in-place BN+ELU on h2 (fast exp) =================
__global__ void __launch_bounds__(256) k_elu(
        __half* __restrict__ h2, const float* __restrict__ ps2,
        const float* __restrict__ psq2, const float* __restrict__ bn2g,
        const float* __restrict__ bn2b) {
    int ch = blockIdx.x, qt = blockIdx.y;
    int tid = threadIdx.x;
    __shared__ double rs[256], rs2[256];
    __shared__ float saf, scf;
    double s = 0.0, s2 = 0.0;
    for (int i = tid; i < NB2; i += 256) {
        s  += (double)ps2 [(size_t)ch * NB2 + i];
        s2 += (double)psq2[(size_t)ch * NB2 + i];
    }
    rs[tid] = s; rs2[tid] = s2;
    __syncthreads();
    for (int off = 128; off > 0; off >>= 1) {
        if (tid < off) { rs[tid] += rs[tid + off]; rs2[tid] += rs2[tid + off]; }
        __syncthreads();
    }
    if (tid == 0) {
        double mu  = rs[0] / NBN2;
        double var = rs2[0] / NBN2 - mu * mu;
        double av  = (double)bn2g[ch] / sqrt(var + 1e-5);
        saf = (float)av;
        scf = bn2b[ch] - (float)(mu * av);
    }
    __syncthreads();
    float a = saf, c = scf;

    for (int idx = tid; idx < 64 * 124; idx += 256) {
        int r = idx / 124, cj = idx - r * 124;
        int b = qt * 64 + r;
        uint4* p = (uint4*)(h2 + ((size_t)b * D2 + ch) * T2P) + cj;
        uint4 v = *p;
        __half* hv = (__half*)&v;
        int tb = cj * 8;
#pragma unroll
        for (int e = 0; e < 8; e++) {
            float f = __half2float(hv[e]);
            f = fmaf(f, a, c);
            f = f > 0.f ? f : (__expf(f) - 1.f);
            if (tb + e >= T2) f = 0.f;
            hv[e] = __float2half_rn(f);
        }
        *p = v;
    }
}

// ================= fused cov (chunked HMMA) + Jacobi (fast-div) + projectors =================
#define CVS 520
#define SMEM_CV (32 * CVS * 2)   // 33280 B dynamic
__global__ void __launch_bounds__(256) k_coveig(
        const __half* __restrict__ h2e,
        const float* __restrict__ wq, const float* __restrict__ wk,
        const float* __restrict__ wv,
        float* __restrict__ QQt, float* __restrict__ KKt,
        float* __restrict__ Vp) {
    extern __shared__ __align__(16) char dsm[];
    __half* sX = (__half*)dsm;
    float* red = (float*)dsm;
    __shared__ float A[32][33], V[32][33];
    __shared__ int sidx[8];
    __shared__ float sUp[32][8], sM[16][8], sG[8][8], sY[16][8];
    int bm = blockIdx.x;
    int b = bm / EP, m = bm - b * EP;
    int tid = threadIdx.x, lane = tid & 31, w = tid >> 5;

    for (int i = tid; i < 1024; i += 256) {
        int r = i >> 5, cc = i & 31;
        V[r][cc] = (r == cc) ? 1.f : 0.f;
    }

    float acc[2][4][4];
#pragma unroll
    for (int mt = 0; mt < 2; mt++)
#pragma unroll
        for (int nt = 0; nt < 4; nt++)
#pragma unroll
            for (int e = 0; e < 4; e++) acc[mt][nt][e] = 0.f;

    uint32_t base = smem_u32(sX);
    uint32_t l7 = lane & 7, bgrp = lane >> 3;
    uint32_t arow = l7 + ((bgrp & 1) << 3);
    uint32_t acol = (bgrp >> 1) << 4;
    uint32_t bcol = (bgrp & 1) << 4;

#pragma unroll 1
    for (int chk = 0; chk < 2; chk++) {
        __syncthreads();
        for (int idx = tid; idx < 32 * 62; idx += 256) {
            int r = idx / 62, cj = idx - r * 62;
            *((uint4*)(sX + r * CVS) + cj) =
                *((const uint4*)(h2e + ((size_t)b * D2 + m * 32 + r) * T2P)
                  + chk * 62 + cj);
        }
        __syncthreads();
        for (int k = w; k < 31; k += 8) {
            uint32_t kb = base + (uint32_t)k * 32;
            uint32_t af[2][4];
#pragma unroll
            for (int mt = 0; mt < 2; mt++)
                LDSM_X4(af[mt][0], af[mt][1], af[mt][2], af[mt][3],
                        kb + (mt * 16 + arow) * (CVS * 2) + acol);
            uint32_t bf[4][2];
#pragma unroll
            for (int nt = 0; nt < 4; nt++)
                LDSM_X2(bf[nt][0], bf[nt][1],
                        kb + (nt * 8 + l7) * (CVS * 2) + bcol);
#pragma unroll
            for (int mt = 0; mt < 2; mt++)
#pragma unroll
                for (int nt = 0; nt < 4; nt++)
                    MMA16816(acc[mt][nt], af[mt][0], af[mt][1], af[mt][2], af[mt][3],
                             bf[nt][0], bf[nt][1]);
        }
    }
    __syncthreads();

    {
        int rb = lane >> 2, cb = 2 * (lane & 3);
        float* rw = red + w * 1024;
#pragma unroll
        for (int mt = 0; mt < 2; mt++)
#pragma unroll
            for (int nt = 0; nt < 4; nt++) {
                int row = mt * 16 + rb, col = nt * 8 + cb;
                rw[row * 32 + col]           = acc[mt][nt][0];
                rw[row * 32 + col + 1]       = acc[mt][nt][1];
                rw[(row + 8) * 32 + col]     = acc[mt][nt][2];
                rw[(row + 8) * 32 + col + 1] = acc[mt][nt][3];
            }
    }
    __syncthreads();
    for (int o = tid; o < 1024; o += 256) {
        float s = 0.f;
#pragma unroll
        for (int k2 = 0; k2 < 8; k2++) s += red[k2 * 1024 + o];
        A[o >> 5][o & 31] = s;
    }
    __syncthreads();

    // ---- Jacobi (threshold-skip, fast division, 2 barriers/round) ----
    {
        int g = tid >> 4, l = tid & 15;
        for (int sw = 0; sw < NSWEEP; sw++) {
            for (int r = 0; r < 31; r++) {
                int p = (g == 0) ? 0 : ((g - 1 + r) % 31) + 1;
                int q = ((30 - g + r) % 31) + 1;
                if (p > q) { int tmp = p; p = q; q = tmp; }
                float app = A[p][p], aqq = A[q][q], apq = A[p][q];
                bool skip = (apq * apq <= 1e-14f * fabsf(app * aqq) + 1e-38f);
                float cv = 1.f, sv = 0.f;
                if (!skip) {
                    float tau = __fdividef(aqq - app, 2.f * apq);
                    float tt = __fdividef((tau >= 0.f ? 1.f : -1.f),
                                          fabsf(tau) + sqrtf(1.f + tau * tau));
                    cv = rsqrtf(1.f + tt * tt);
                    sv = tt * cv;
                }
                if (!skip) {
                    float ap = A[p][l], aq = A[q][l];
                    A[p][l] = cv * ap - sv * aq;
                    A[q][l] = sv * ap + cv * aq;
                    int j1 = l + 16;
                    ap = A[p][j1]; aq = A[q][j1];
                    A[p][j1] = cv * ap - sv * aq;
                    A[q][j1] = sv * ap + cv * aq;
                }
                __syncthreads();
                if (!skip) {
#pragma unroll
                    for (int s2 = 0; s2 < 2; s2++) {
                        int ii = l + 16 * s2;
                        float ap = A[ii][p], aq = A[ii][q];
                        A[ii][p] = cv * ap - sv * aq;
                        A[ii][q] = sv * ap + cv * aq;
                        float vp = V[ii][p], vq = V[ii][q];
                        V[ii][p] = cv * vp - sv * vq;
                        V[ii][q] = sv * vp + cv * vq;
                    }
                }
                __syncthreads();
            }
        }
    }

    if (tid == 0) {
        float vals[32];
        for (int i = 0; i < 32; i++) vals[i] = A[i][i];
        for (int j = 0; j < 8; j++) {
            int am = 0; float mv = vals[0];
            for (int i = 1; i < 32; i++) if (vals[i] > mv) { mv = vals[i]; am = i; }
            sidx[j] = am; vals[am] = -3.4e38f;
        }
    }
    __syncthreads();
    sUp[tid >> 3][tid & 7] = V[tid >> 3][sidx[tid & 7]];
    __syncthreads();

    // ---- projectors ----
    int nmat = (m == 2) ? 3 : 2;
    for (int mat = 0; mat < nmat; mat++) {
        const float* W = (mat == 0) ? wq : (mat == 1) ? wk : wv;
        if (tid < 128) {
            int r = tid >> 3, p = tid & 7;
            float s = 0.f;
            for (int cc = 0; cc < 32; cc++) s = fmaf(W[r * 32 + cc], sUp[cc][p], s);
            sM[r][p] = s;
        }
        __syncthreads();
        if (tid < 64) {
            int i = tid >> 3, j = tid & 7;
            float s = 0.f;
            for (int rr = 0; rr < 16; rr++) s = fmaf(sM[rr][i], sM[rr][j], s);
            sG[i][j] = s;
        }
        __syncthreads();
        if (tid == 0) {
            for (int k = 0; k < 8; k++) {
                float lkk = sqrtf(sG[k][k]);
                sG[k][k] = lkk;
                float inv = 1.f / lkk;
                for (int i = k + 1; i < 8; i++) sG[i][k] *= inv;
                for (int j = k + 1; j < 8; j++)
                    for (int i = j; i < 8; i++) sG[i][j] -= sG[i][k] * sG[j][k];
            }
        }
        __syncthreads();
        if (tid < 16) {
            int r = tid;
            for (int i = 0; i < 8; i++) {
                float v = sM[r][i];
                for (int j = 0; j < i; j++) v -= sG[i][j] * sY[r][j];
                sY[r][i] = v / sG[i][i];
            }
        }
        __syncthreads();
        float* outp = (mat == 0) ? (QQt + bm * 256)
                    : (mat == 1) ? (KKt + bm * 256)
                                 : (Vp + b * 256);
        {
            int u = tid >> 4, v = tid & 15;
            float s = 0.f;
#pragma unroll
            for (int i = 0; i < 8; i++) s = fmaf(sY[u][i], sY[v][i], s);
            outp[tid] = s;
        }
        __syncthreads();
    }
}

// ================= E, softmax, final linear =================
__global__ void k_final(const float* __restrict__ QQt, const float* __restrict__ KKt,
                        const float* __restrict__ Vp, const float* __restrict__ lw,
                        const float* __restrict__ lb, float* __restrict__ out) {
    int b = blockIdx.x, tid = threadIdx.x;
    __shared__ float sQ[3 * 256], sK[3 * 256], sV[256];
    __shared__ float sE[9], swv[3];
    __shared__ float red[8];
    __shared__ float red12[12][8];
    for (int i = tid; i < 768; i += 256) {
        sQ[i] = QQt[b * 768 + i];
        sK[i] = KKt[b * 768 + i];
    }
    sV[tid] = Vp[b * 256 + tid];
    __syncthreads();

    int u = tid >> 4, v = tid & 15;
    for (int ij = 0; ij < 9; ij++) {
        int i = ij / 3, j = ij - 3 * i;
        const float* Qj = sQ + j * 256;
        const float* Ki = sK + i * 256;
        float dd = 0.f;
#pragma unroll
        for (int w = 0; w < 16; w++) {
            float du = Qj[u * 16 + w] - Ki[u * 16 + w];
            float dv = Qj[v * 16 + w] - Ki[v * 16 + w];
            dd = fmaf(du, dv, dd);
        }
        float val = dd * dd;
        for (int off = 16; off > 0; off >>= 1) val += __shfl_down_sync(0xffffffffu, val, off);
        if ((tid & 31) == 0) red[tid >> 5] = val;
        __syncthreads();
        if (tid == 0) {
            float s = 0.f;
            for (int w = 0; w < 8; w++) s += red[w];
            sE[ij] = sqrtf(s);
        }
        __syncthreads();
    }
    if (tid == 0) {
        for (int j = 0; j < 3; j++) {
            float s0 = 1.f / (1.f + log1pf(sE[0 * 3 + j]));
            float s1 = 1.f / (1.f + log1pf(sE[1 * 3 + j]));
            float s2 = 1.f / (1.f + log1pf(sE[2 * 3 + j]));
            float mx = fmaxf(s0, fmaxf(s1, s2));
            float e0 = expf(s0 - mx), e1 = expf(s1 - mx), e2 = expf(s2 - mx);
            swv[j] = e2 / (e0 + e1 + e2);
        }
    }
    __syncthreads();

    float vv = sV[tid];
    float part[12];
#pragma unroll
    for (int r = 0; r < 4; r++)
#pragma unroll
        for (int j = 0; j < 3; j++)
            part[r * 3 + j] = lw[r * 768 + j * 256 + tid] * vv;
#pragma unroll
    for (int kk = 0; kk < 12; kk++) {
        float val = part[kk];
        for (int off = 16; off > 0; off >>= 1) val += __shfl_down_sync(0xffffffffu, val, off);
        if ((tid & 31) == 0) red12[kk][tid >> 5] = val;
    }
    __syncthreads();
    if (tid < 4) {
        float o = lb[tid];
        for (int j = 0; j < 3; j++) {
            float ds = 0.f;
            for (int w = 0; w < 8; w++) ds += red12[tid * 3 + j][w];
            o = fmaf(swv[j], ds, o);
        }
        out[b * 4 + tid] = o;
    }
}

// ================= launch =================
extern "C" void kernel_launch(void* const* d_in, const int* in_sizes, int n_in,
                              void* d_out, int out_size) {
    const float* x      = (const float*)d_in[0];
    const float* conv1w = (const float*)d_in[1];
    const float* bn1g   = (const float*)d_in[3];
    const float* bn1b   = (const float*)d_in[4];
    const float* conv2w = (const float*)d_in[5];
    const float* bn2g   = (const float*)d_in[7];
    const float* bn2b   = (const float*)d_in[8];
    const float* wq     = (const float*)d_in[9];
    const float* wk     = (const float*)d_in[10];
    const float* wv     = (const float*)d_in[11];
    const float* linw   = (const float*)d_in[12];
    const float* linb   = (const float*)d_in[13];
    float* out = (float*)d_out;

    float *QQt, *KKt, *Vp, *ps1, *ps1q, *ps2, *ps2q, *w1p, *c1f;
    __half *aw, *h2;
    cudaGetSymbolAddress((void**)&h2,  g_h2);
    cudaGetSymbolAddress((void**)&QQt, g_QQt);
    cudaGetSymbolAddress((void**)&KKt, g_KKt);
    cudaGetSymbolAddress((void**)&Vp,  g_Vp);
    cudaGetSymbolAddress((void**)&ps1, g_ps1);
    cudaGetSymbolAddress((void**)&ps1q,g_ps1q);
    cudaGetSymbolAddress((void**)&ps2, g_ps2);
    cudaGetSymbolAddress((void**)&ps2q,g_ps2q);
    cudaGetSymbolAddress((void**)&aw,  g_Aw);
    cudaGetSymbolAddress((void**)&w1p, g_W1p);
    cudaGetSymbolAddress((void**)&c1f, g_c1f);

    cudaFuncSetAttribute(k_conv2_hmma, cudaFuncAttributeMaxDynamicSharedMemorySize, SMEM_C2);
    cudaFuncSetAttribute(k_coveig, cudaFuncAttributeMaxDynamicSharedMemorySize, SMEM_CV);

    k_conv1s    <<<NB1, 128>>>(x, conv1w, ps1, ps1q);
    k_finprep   <<<34, 256>>>(ps1, ps1q, bn1g, bn1b, conv1w, conv2w, w1p, c1f, aw);
    k_conv2_hmma<<<dim3(BS, 4), 512, SMEM_C2>>>(x, aw, w1p, c1f, h2, ps2, ps2q);
    k_elu       <<<dim3(D2, 4), 256>>>(h2, ps2, ps2q, bn2g, bn2b);
    k_coveig    <<<BS * EP, 256, SMEM_CV>>>(h2, wq, wk, wv, QQt, KKt, Vp);
    k_final     <<<BS, 256>>>(QQt, KKt, Vp, linw, linb, out);
}